// round 1
// baseline (speedup 1.0000x reference)
#include <cuda_runtime.h>
#include <math.h>

#define E  4096
#define Hh 32
#define Mm 256
#define Bb 8
#define Nn 256
#define Dd 128

// ---------------- scratch (alloc-free: __device__ globals) ----------------
__device__ float g_kv[Bb * Nn * E];     // LN(x)
__device__ float g_qin[Mm * E];         // LN(query) + pos
__device__ float g_Q[Mm * E];
__device__ float g_K[Bb * Nn * E];
__device__ float g_V[Bb * Nn * E];
__device__ float g_O[Bb * Mm * E];
__device__ float g_attn[Bb * Hh * Mm * Nn];

// ---------------- LayerNorm (one row per block, optional +pos) ----------------
__global__ void __launch_bounds__(256) ln_kernel(
    const float* __restrict__ x, const float* __restrict__ w,
    const float* __restrict__ bias, const float* __restrict__ pos,
    float* __restrict__ out)
{
    int row = blockIdx.x;
    int tid = threadIdx.x;
    const float4* xr = (const float4*)(x + (size_t)row * E);
    float4 v[4];
    float s = 0.f, sq = 0.f;
#pragma unroll
    for (int i = 0; i < 4; i++) {
        v[i] = xr[tid + 256 * i];
        s  += v[i].x + v[i].y + v[i].z + v[i].w;
        sq += v[i].x * v[i].x + v[i].y * v[i].y + v[i].z * v[i].z + v[i].w * v[i].w;
    }
    __shared__ float s1[256], s2[256];
    s1[tid] = s; s2[tid] = sq;
    __syncthreads();
    for (int st = 128; st > 0; st >>= 1) {
        if (tid < st) { s1[tid] += s1[tid + st]; s2[tid] += s2[tid + st]; }
        __syncthreads();
    }
    float mean = s1[0] * (1.f / E);
    float var  = s2[0] * (1.f / E) - mean * mean;
    float rstd = rsqrtf(var + 1e-5f);

    const float4* wr = (const float4*)w;
    const float4* br = (const float4*)bias;
    const float4* pr = pos ? (const float4*)(pos + (size_t)row * E) : nullptr;
    float4* orow = (float4*)(out + (size_t)row * E);
#pragma unroll
    for (int i = 0; i < 4; i++) {
        int c = tid + 256 * i;
        float4 ww = wr[c], bb = br[c];
        float4 o;
        o.x = (v[i].x - mean) * rstd * ww.x + bb.x;
        o.y = (v[i].y - mean) * rstd * ww.y + bb.y;
        o.z = (v[i].z - mean) * rstd * ww.z + bb.z;
        o.w = (v[i].w - mean) * rstd * ww.w + bb.w;
        if (pr) {
            float4 p = pr[c];
            o.x += p.x; o.y += p.y; o.z += p.z; o.w += p.w;
        }
        orow[c] = o;
    }
}

// ---------------- big projection GEMM: C(rows x 4096) = A @ W^T + bias ----------------
// A row-major (rows, E), W row-major (E, E) [C = A * W^T], 128x128x32 tile, 8x8/thread.
// ADDPOS: A' = A + pos_embed[(global row) % Nn]  (used for the K projection).
template <bool ADDPOS>
__global__ void __launch_bounds__(256) gemm_proj(
    const float* __restrict__ A, const float* __restrict__ W,
    const float* __restrict__ bias, const float* __restrict__ pos,
    float* __restrict__ C)
{
    const int BK = 32;
    __shared__ float As[BK][132];
    __shared__ float Bs[BK][132];
    int tid = threadIdx.x;
    int m0 = blockIdx.y * 128;
    int n0 = blockIdx.x * 128;
    int tm = (tid >> 4) * 8;
    int tn = (tid & 15) * 8;
    float acc[8][8] = {};

    for (int kt = 0; kt < E; kt += BK) {
#pragma unroll
        for (int i = 0; i < 4; i++) {
            int idx = tid + 256 * i;
            int row = idx >> 3;
            int k   = (idx & 7) * 4;
            float4 a = *(const float4*)(A + (size_t)(m0 + row) * E + kt + k);
            if (ADDPOS) {
                float4 p = *(const float4*)(pos + (size_t)((m0 + row) & (Nn - 1)) * E + kt + k);
                a.x += p.x; a.y += p.y; a.z += p.z; a.w += p.w;
            }
            As[k + 0][row] = a.x; As[k + 1][row] = a.y;
            As[k + 2][row] = a.z; As[k + 3][row] = a.w;
            float4 bv = *(const float4*)(W + (size_t)(n0 + row) * E + kt + k);
            Bs[k + 0][row] = bv.x; Bs[k + 1][row] = bv.y;
            Bs[k + 2][row] = bv.z; Bs[k + 3][row] = bv.w;
        }
        __syncthreads();
#pragma unroll
        for (int kk = 0; kk < BK; kk++) {
            float a[8], b[8];
            *(float4*)&a[0] = *(const float4*)&As[kk][tm];
            *(float4*)&a[4] = *(const float4*)&As[kk][tm + 4];
            *(float4*)&b[0] = *(const float4*)&Bs[kk][tn];
            *(float4*)&b[4] = *(const float4*)&Bs[kk][tn + 4];
#pragma unroll
            for (int i = 0; i < 8; i++)
#pragma unroll
                for (int j = 0; j < 8; j++)
                    acc[i][j] += a[i] * b[j];
        }
        __syncthreads();
    }

    float bb[8];
    *(float4*)&bb[0] = *(const float4*)(bias + n0 + tn);
    *(float4*)&bb[4] = *(const float4*)(bias + n0 + tn + 4);
#pragma unroll
    for (int i = 0; i < 8; i++) {
        float* cp = C + (size_t)(m0 + tm + i) * E + n0 + tn;
        float4 o0 = make_float4(acc[i][0] + bb[0], acc[i][1] + bb[1],
                                acc[i][2] + bb[2], acc[i][3] + bb[3]);
        float4 o1 = make_float4(acc[i][4] + bb[4], acc[i][5] + bb[5],
                                acc[i][6] + bb[6], acc[i][7] + bb[7]);
        *(float4*)cp = o0;
        *(float4*)(cp + 4) = o1;
    }
}

// ---------------- scores: S[b,h,m,n] = (Q_h[m,:] . K_bh[n,:]) / sqrt(D) ----------------
__global__ void __launch_bounds__(256) attn_score(
    const float* __restrict__ Q, const float* __restrict__ K, float* __restrict__ attn)
{
    const int BK = 16;
    __shared__ float As[BK][68];
    __shared__ float Bs[BK][68];
    int tid = threadIdx.x;
    int bh = blockIdx.z;
    int h = bh & (Hh - 1);
    int b = bh >> 5;
    int m0 = blockIdx.y * 64;
    int n0 = blockIdx.x * 64;
    const float* Qb = Q + h * Dd;
    const float* Kb = K + (size_t)b * Nn * E + h * Dd;
    int tm = (tid >> 4) * 4, tn = (tid & 15) * 4;
    int row = tid >> 2;
    int k4  = (tid & 3) * 4;
    float acc[4][4] = {};

    for (int kt = 0; kt < Dd; kt += BK) {
        float4 a = *(const float4*)(Qb + (size_t)(m0 + row) * E + kt + k4);
        As[k4 + 0][row] = a.x; As[k4 + 1][row] = a.y;
        As[k4 + 2][row] = a.z; As[k4 + 3][row] = a.w;
        float4 bv = *(const float4*)(Kb + (size_t)(n0 + row) * E + kt + k4);
        Bs[k4 + 0][row] = bv.x; Bs[k4 + 1][row] = bv.y;
        Bs[k4 + 2][row] = bv.z; Bs[k4 + 3][row] = bv.w;
        __syncthreads();
#pragma unroll
        for (int kk = 0; kk < BK; kk++) {
            float a4[4], b4[4];
            *(float4*)a4 = *(const float4*)&As[kk][tm];
            *(float4*)b4 = *(const float4*)&Bs[kk][tn];
#pragma unroll
            for (int i = 0; i < 4; i++)
#pragma unroll
                for (int j = 0; j < 4; j++)
                    acc[i][j] += a4[i] * b4[j];
        }
        __syncthreads();
    }
    const float scale = 0.08838834764831845f;  // 1/sqrt(128)
#pragma unroll
    for (int i = 0; i < 4; i++) {
        float4 o = make_float4(acc[i][0] * scale, acc[i][1] * scale,
                               acc[i][2] * scale, acc[i][3] * scale);
        *(float4*)(attn + ((size_t)bh * Mm + m0 + tm + i) * Nn + n0 + tn) = o;
    }
}

// ---------------- softmax over n (warp per row of 256) ----------------
__global__ void __launch_bounds__(256) softmax_kernel(float* __restrict__ attn)
{
    int warp = threadIdx.x >> 5, lane = threadIdx.x & 31;
    size_t row = (size_t)blockIdx.x * 8 + warp;
    float4* p = (float4*)(attn + row * Nn);
    float4 v0 = p[lane];
    float4 v1 = p[lane + 32];
    float mx = fmaxf(fmaxf(fmaxf(v0.x, v0.y), fmaxf(v0.z, v0.w)),
                     fmaxf(fmaxf(v1.x, v1.y), fmaxf(v1.z, v1.w)));
#pragma unroll
    for (int o = 16; o; o >>= 1) mx = fmaxf(mx, __shfl_xor_sync(0xffffffffu, mx, o));
    v0.x = expf(v0.x - mx); v0.y = expf(v0.y - mx);
    v0.z = expf(v0.z - mx); v0.w = expf(v0.w - mx);
    v1.x = expf(v1.x - mx); v1.y = expf(v1.y - mx);
    v1.z = expf(v1.z - mx); v1.w = expf(v1.w - mx);
    float s = v0.x + v0.y + v0.z + v0.w + v1.x + v1.y + v1.z + v1.w;
#pragma unroll
    for (int o = 16; o; o >>= 1) s += __shfl_xor_sync(0xffffffffu, s, o);
    float inv = 1.f / s;
    v0.x *= inv; v0.y *= inv; v0.z *= inv; v0.w *= inv;
    v1.x *= inv; v1.y *= inv; v1.z *= inv; v1.w *= inv;
    p[lane] = v0;
    p[lane + 32] = v1;
}

// ---------------- O[b,m,h,d] = sum_n attn[b,h,m,n] * V[b,n,h,d] ----------------
__global__ void __launch_bounds__(256) attn_out(
    const float* __restrict__ attn, const float* __restrict__ V, float* __restrict__ O)
{
    const int BK = 16;
    __shared__ float As[BK][68];  // [n][m]
    __shared__ float Bs[BK][68];  // [n][d]
    int tid = threadIdx.x;
    int bh = blockIdx.z;
    int h = bh & (Hh - 1);
    int b = bh >> 5;
    int m0 = blockIdx.y * 64;
    int d0 = blockIdx.x * 64;
    const float* Ab = attn + (size_t)bh * Mm * Nn;
    const float* Vb = V + (size_t)b * Nn * E + h * Dd;
    int tm = (tid >> 4) * 4, tn = (tid & 15) * 4;
    int arow = tid >> 2, ak4 = (tid & 3) * 4;
    int bk = tid >> 4, bd4 = (tid & 15) * 4;
    float acc[4][4] = {};

    for (int kt = 0; kt < Nn; kt += BK) {
        float4 a = *(const float4*)(Ab + (size_t)(m0 + arow) * Nn + kt + ak4);
        As[ak4 + 0][arow] = a.x; As[ak4 + 1][arow] = a.y;
        As[ak4 + 2][arow] = a.z; As[ak4 + 3][arow] = a.w;
        float4 bv = *(const float4*)(Vb + (size_t)(kt + bk) * E + d0 + bd4);
        *(float4*)&Bs[bk][bd4] = bv;
        __syncthreads();
#pragma unroll
        for (int kk = 0; kk < BK; kk++) {
            float a4[4], b4[4];
            *(float4*)a4 = *(const float4*)&As[kk][tm];
            *(float4*)b4 = *(const float4*)&Bs[kk][tn];
#pragma unroll
            for (int i = 0; i < 4; i++)
#pragma unroll
                for (int j = 0; j < 4; j++)
                    acc[i][j] += a4[i] * b4[j];
        }
        __syncthreads();
    }
#pragma unroll
    for (int i = 0; i < 4; i++) {
        float4 o = make_float4(acc[i][0], acc[i][1], acc[i][2], acc[i][3]);
        *(float4*)(O + ((size_t)b * Mm + m0 + tm + i) * E + h * Dd + d0 + tn) = o;
    }
}

// ---------------- attn mean over heads ----------------
__global__ void __launch_bounds__(256) attn_mean_kernel(
    const float* __restrict__ attn, float* __restrict__ out)
{
    int idx = blockIdx.x * 256 + threadIdx.x;  // over B*M*N
    int b = idx / (Mm * Nn);
    int rem = idx - b * (Mm * Nn);
    const float* p = attn + (size_t)b * Hh * Mm * Nn + rem;
    float s = 0.f;
#pragma unroll
    for (int h = 0; h < Hh; h++) s += p[(size_t)h * Mm * Nn];
    out[idx] = s * (1.f / Hh);
}

// ---------------- launcher ----------------
extern "C" void kernel_launch(void* const* d_in, const int* in_sizes, int n_in,
                              void* d_out, int out_size)
{
    const float* x       = (const float*)d_in[0];
    const float* query   = (const float*)d_in[1];
    const float* pos     = (const float*)d_in[2];
    const float* ln_q_w  = (const float*)d_in[3];
    const float* ln_q_b  = (const float*)d_in[4];
    const float* ln_kv_w = (const float*)d_in[5];
    const float* ln_kv_b = (const float*)d_in[6];
    const float* in_w    = (const float*)d_in[7];
    const float* in_b    = (const float*)d_in[8];
    const float* out_w   = (const float*)d_in[9];
    const float* out_b   = (const float*)d_in[10];
    float* out = (float*)d_out;

    float *kv, *qin, *Qp, *Kp, *Vp, *Op, *attn;
    cudaGetSymbolAddress((void**)&kv,   g_kv);
    cudaGetSymbolAddress((void**)&qin,  g_qin);
    cudaGetSymbolAddress((void**)&Qp,   g_Q);
    cudaGetSymbolAddress((void**)&Kp,   g_K);
    cudaGetSymbolAddress((void**)&Vp,   g_V);
    cudaGetSymbolAddress((void**)&Op,   g_O);
    cudaGetSymbolAddress((void**)&attn, g_attn);

    // 1) LayerNorms (q gets pos-embed fused)
    ln_kernel<<<Bb * Nn, 256>>>(x, ln_kv_w, ln_kv_b, nullptr, kv);
    ln_kernel<<<Mm, 256>>>(query, ln_q_w, ln_q_b, pos, qin);

    // 2) Projections: Q = qin@Wq^T+bq; K = (kv+pos)@Wk^T+bk; V = kv@Wv^T+bv
    gemm_proj<false><<<dim3(32, 2), 256>>>(qin, in_w, in_b, nullptr, Qp);
    gemm_proj<true><<<dim3(32, 16), 256>>>(kv, in_w + (size_t)E * E, in_b + E, pos, Kp);
    gemm_proj<false><<<dim3(32, 16), 256>>>(kv, in_w + (size_t)2 * E * E, in_b + 2 * E, nullptr, Vp);

    // 3) Attention
    attn_score<<<dim3(4, 4, Bb * Hh), 256>>>(Qp, Kp, attn);
    softmax_kernel<<<Bb * Hh * Mm / 8, 256>>>(attn);
    attn_out<<<dim3(2, 4, Bb * Hh), 256>>>(attn, Vp, Op);

    // 4) Output projection -> d_out[0 : B*M*E)
    gemm_proj<false><<<dim3(32, 16), 256>>>(Op, out_w, out_b, nullptr, out);

    // 5) attn.mean(heads) -> d_out[B*M*E : B*M*E + B*M*N)
    attn_mean_kernel<<<Bb * Mm * Nn / 256, 256>>>(attn, out + (size_t)Bb * Mm * E);
}

// round 3
// speedup vs baseline: 1.9330x; 1.9330x over previous
#include <cuda_runtime.h>
#include <cuda_bf16.h>
#include <cstdint>
#include <math.h>

#define E  4096
#define Hh 32
#define Mm 256
#define Bb 8
#define Nn 256
#define Dd 128

// ---------------- scratch (alloc-free: __device__ globals) ----------------
__device__ float g_kv[Bb * Nn * E];     // LN(x)
__device__ float g_qin[Mm * E];         // LN(query) + pos
__device__ float g_Q[Mm * E];
__device__ float g_K[Bb * Nn * E];
__device__ float g_V[Bb * Nn * E];
__device__ float g_O[Bb * Mm * E];
__device__ float g_attn[Bb * Hh * Mm * Nn];

// ---------------- helpers ----------------
__device__ __forceinline__ void mma16816(float* d, const uint32_t* a, const uint32_t* b) {
    asm volatile(
        "mma.sync.aligned.m16n8k16.row.col.f32.bf16.bf16.f32 "
        "{%0,%1,%2,%3}, {%4,%5,%6,%7}, {%8,%9}, {%0,%1,%2,%3};"
        : "+f"(d[0]), "+f"(d[1]), "+f"(d[2]), "+f"(d[3])
        : "r"(a[0]), "r"(a[1]), "r"(a[2]), "r"(a[3]), "r"(b[0]), "r"(b[1]));
}

// fp32x4 -> bf16 hi/lo split, packed as 4+4 bf16 (uint2 each)
__device__ __forceinline__ void split_f4(float4 v, uint2& hi, uint2& lo) {
    __nv_bfloat162 h0, h1, l0, l1;
    h0.x = __float2bfloat16_rn(v.x); h0.y = __float2bfloat16_rn(v.y);
    h1.x = __float2bfloat16_rn(v.z); h1.y = __float2bfloat16_rn(v.w);
    l0.x = __float2bfloat16_rn(v.x - __bfloat162float(h0.x));
    l0.y = __float2bfloat16_rn(v.y - __bfloat162float(h0.y));
    l1.x = __float2bfloat16_rn(v.z - __bfloat162float(h1.x));
    l1.y = __float2bfloat16_rn(v.w - __bfloat162float(h1.y));
    hi.x = *(uint32_t*)&h0; hi.y = *(uint32_t*)&h1;
    lo.x = *(uint32_t*)&l0; lo.y = *(uint32_t*)&l1;
}

// ======================= HMMA projection GEMM =======================
// C(128x128 tile) = A @ W^T + bias, K=E, split-bf16 3-pass, fp32 accum.
// smem per buffer: Ah, Al, Bh, Bl each [128][40] bf16 (pad 8 -> conflict-free frags)
#define ROWP 40
#define TILE_B (128 * ROWP * 2)          // 10240 B
#define BUF_B  (4 * TILE_B)              // 40960 B
#define GEMM_SMEM_BYTES (2 * BUF_B)      // 81920 B

template <bool ADDPOS>
__global__ void __launch_bounds__(256) gemm_mma(
    const float* __restrict__ A, const float* __restrict__ W,
    const float* __restrict__ bias, const float* __restrict__ pos,
    float* __restrict__ C)
{
    extern __shared__ __nv_bfloat16 sm[];
    const int tid  = threadIdx.x;
    const int wid  = tid >> 5;
    const int lane = tid & 31;
    const int g    = lane >> 2;      // group row
    const int tq   = lane & 3;       // thread-in-group (col pair)
    const int wm   = (wid >> 1) * 32;
    const int wn   = (wid & 1) * 64;
    const int m0 = blockIdx.y * 128;
    const int n0 = blockIdx.x * 128;

    float acc[2][8][4];
#pragma unroll
    for (int i = 0; i < 2; i++)
#pragma unroll
        for (int j = 0; j < 8; j++)
#pragma unroll
            for (int k = 0; k < 4; k++) acc[i][j][k] = 0.f;

    const int NIT = E / 32;
    float4 va[4], vb[4];

    // preload tile 0
#pragma unroll
    for (int j = 0; j < 4; j++) {
        int i = tid + 256 * j;
        int row = i >> 3;
        int col = (i & 7) * 4;
        va[j] = *(const float4*)(A + (size_t)(m0 + row) * E + col);
        if (ADDPOS) {
            float4 p = *(const float4*)(pos + (size_t)((m0 + row) & (Nn - 1)) * E + col);
            va[j].x += p.x; va[j].y += p.y; va[j].z += p.z; va[j].w += p.w;
        }
        vb[j] = *(const float4*)(W + (size_t)(n0 + row) * E + col);
    }
    {
        __nv_bfloat16* Ah = sm;
        __nv_bfloat16* Al = sm + TILE_B / 2;
        __nv_bfloat16* Bh = sm + 2 * (TILE_B / 2);
        __nv_bfloat16* Bl = sm + 3 * (TILE_B / 2);
#pragma unroll
        for (int j = 0; j < 4; j++) {
            int i = tid + 256 * j;
            int row = i >> 3;
            int col = (i & 7) * 4;
            uint2 hi, lo;
            split_f4(va[j], hi, lo);
            *(uint2*)(Ah + row * ROWP + col) = hi;
            *(uint2*)(Al + row * ROWP + col) = lo;
            split_f4(vb[j], hi, lo);
            *(uint2*)(Bh + row * ROWP + col) = hi;
            *(uint2*)(Bl + row * ROWP + col) = lo;
        }
    }
    __syncthreads();

    for (int c = 0; c < NIT; c++) {
        // prefetch next tile into regs
        if (c + 1 < NIT) {
            int kt = (c + 1) * 32;
#pragma unroll
            for (int j = 0; j < 4; j++) {
                int i = tid + 256 * j;
                int row = i >> 3;
                int col = (i & 7) * 4;
                va[j] = *(const float4*)(A + (size_t)(m0 + row) * E + kt + col);
                if (ADDPOS) {
                    float4 p = *(const float4*)(pos + (size_t)((m0 + row) & (Nn - 1)) * E + kt + col);
                    va[j].x += p.x; va[j].y += p.y; va[j].z += p.z; va[j].w += p.w;
                }
                vb[j] = *(const float4*)(W + (size_t)(n0 + row) * E + kt + col);
            }
        }

        // compute current buffer
        const __nv_bfloat16* base = sm + (size_t)(c & 1) * (BUF_B / 2);
        const __nv_bfloat16* Ah = base;
        const __nv_bfloat16* Al = base + TILE_B / 2;
        const __nv_bfloat16* Bh = base + 2 * (TILE_B / 2);
        const __nv_bfloat16* Bl = base + 3 * (TILE_B / 2);
#pragma unroll
        for (int ks = 0; ks < 32; ks += 16) {
            uint32_t ah[2][4], al[2][4], bf[8][2];
#pragma unroll
            for (int mt = 0; mt < 2; mt++)
#pragma unroll
                for (int r = 0; r < 4; r++) {
                    int row = wm + mt * 16 + g + (r & 1) * 8;
                    int col = ks + tq * 2 + (r >> 1) * 8;
                    ah[mt][r] = *(const uint32_t*)(Ah + row * ROWP + col);
                    al[mt][r] = *(const uint32_t*)(Al + row * ROWP + col);
                }
#pragma unroll
            for (int nt = 0; nt < 8; nt++) {
                int row = wn + nt * 8 + g;
                bf[nt][0] = *(const uint32_t*)(Bh + row * ROWP + ks + tq * 2);
                bf[nt][1] = *(const uint32_t*)(Bh + row * ROWP + ks + tq * 2 + 8);
            }
            // pass 1: Ah*Bh ; pass 2: Al*Bh (Bh regs still live)
#pragma unroll
            for (int mt = 0; mt < 2; mt++)
#pragma unroll
                for (int nt = 0; nt < 8; nt++) mma16816(acc[mt][nt], ah[mt], bf[nt]);
#pragma unroll
            for (int mt = 0; mt < 2; mt++)
#pragma unroll
                for (int nt = 0; nt < 8; nt++) mma16816(acc[mt][nt], al[mt], bf[nt]);
            // pass 3: Ah*Bl
#pragma unroll
            for (int nt = 0; nt < 8; nt++) {
                int row = wn + nt * 8 + g;
                bf[nt][0] = *(const uint32_t*)(Bl + row * ROWP + ks + tq * 2);
                bf[nt][1] = *(const uint32_t*)(Bl + row * ROWP + ks + tq * 2 + 8);
            }
#pragma unroll
            for (int mt = 0; mt < 2; mt++)
#pragma unroll
                for (int nt = 0; nt < 8; nt++) mma16816(acc[mt][nt], ah[mt], bf[nt]);
        }

        // store prefetched tile into other buffer
        if (c + 1 < NIT) {
            __nv_bfloat16* nb = sm + (size_t)((c + 1) & 1) * (BUF_B / 2);
            __nv_bfloat16* nAh = nb;
            __nv_bfloat16* nAl = nb + TILE_B / 2;
            __nv_bfloat16* nBh = nb + 2 * (TILE_B / 2);
            __nv_bfloat16* nBl = nb + 3 * (TILE_B / 2);
#pragma unroll
            for (int j = 0; j < 4; j++) {
                int i = tid + 256 * j;
                int row = i >> 3;
                int col = (i & 7) * 4;
                uint2 hi, lo;
                split_f4(va[j], hi, lo);
                *(uint2*)(nAh + row * ROWP + col) = hi;
                *(uint2*)(nAl + row * ROWP + col) = lo;
                split_f4(vb[j], hi, lo);
                *(uint2*)(nBh + row * ROWP + col) = hi;
                *(uint2*)(nBl + row * ROWP + col) = lo;
            }
        }
        __syncthreads();
    }

    // epilogue: bias + store
    float bn[8][2];
#pragma unroll
    for (int nt = 0; nt < 8; nt++) {
        int n = n0 + wn + nt * 8 + tq * 2;
        bn[nt][0] = bias[n];
        bn[nt][1] = bias[n + 1];
    }
#pragma unroll
    for (int mt = 0; mt < 2; mt++)
#pragma unroll
        for (int half = 0; half < 2; half++) {
            int m = m0 + wm + mt * 16 + g + half * 8;
            float* cp = C + (size_t)m * E + n0 + wn;
#pragma unroll
            for (int nt = 0; nt < 8; nt++) {
                float2 v;
                v.x = acc[mt][nt][half * 2 + 0] + bn[nt][0];
                v.y = acc[mt][nt][half * 2 + 1] + bn[nt][1];
                *(float2*)(cp + nt * 8 + tq * 2) = v;
            }
        }
}

// ---------------- LayerNorm (one row per block, optional +pos) ----------------
__global__ void __launch_bounds__(256) ln_kernel(
    const float* __restrict__ x, const float* __restrict__ w,
    const float* __restrict__ bias, const float* __restrict__ pos,
    float* __restrict__ out)
{
    int row = blockIdx.x;
    int tid = threadIdx.x;
    const float4* xr = (const float4*)(x + (size_t)row * E);
    float4 v[4];
    float s = 0.f, sq = 0.f;
#pragma unroll
    for (int i = 0; i < 4; i++) {
        v[i] = xr[tid + 256 * i];
        s  += v[i].x + v[i].y + v[i].z + v[i].w;
        sq += v[i].x * v[i].x + v[i].y * v[i].y + v[i].z * v[i].z + v[i].w * v[i].w;
    }
    __shared__ float s1[256], s2[256];
    s1[tid] = s; s2[tid] = sq;
    __syncthreads();
    for (int st = 128; st > 0; st >>= 1) {
        if (tid < st) { s1[tid] += s1[tid + st]; s2[tid] += s2[tid + st]; }
        __syncthreads();
    }
    float mean = s1[0] * (1.f / E);
    float var  = s2[0] * (1.f / E) - mean * mean;
    float rstd = rsqrtf(var + 1e-5f);

    const float4* wr = (const float4*)w;
    const float4* br = (const float4*)bias;
    const float4* pr = pos ? (const float4*)(pos + (size_t)row * E) : nullptr;
    float4* orow = (float4*)(out + (size_t)row * E);
#pragma unroll
    for (int i = 0; i < 4; i++) {
        int c = tid + 256 * i;
        float4 ww = wr[c], bb = br[c];
        float4 o;
        o.x = (v[i].x - mean) * rstd * ww.x + bb.x;
        o.y = (v[i].y - mean) * rstd * ww.y + bb.y;
        o.z = (v[i].z - mean) * rstd * ww.z + bb.z;
        o.w = (v[i].w - mean) * rstd * ww.w + bb.w;
        if (pr) {
            float4 p = pr[c];
            o.x += p.x; o.y += p.y; o.z += p.z; o.w += p.w;
        }
        orow[c] = o;
    }
}

// ---------------- scores: S[b,h,m,n] = (Q_h[m,:] . K_bh[n,:]) / sqrt(D) ----------------
__global__ void __launch_bounds__(256) attn_score(
    const float* __restrict__ Q, const float* __restrict__ K, float* __restrict__ attn)
{
    const int BK = 16;
    __shared__ float As[BK][68];
    __shared__ float Bs[BK][68];
    int tid = threadIdx.x;
    int bh = blockIdx.z;
    int h = bh & (Hh - 1);
    int b = bh >> 5;
    int m0 = blockIdx.y * 64;
    int n0 = blockIdx.x * 64;
    const float* Qb = Q + h * Dd;
    const float* Kb = K + (size_t)b * Nn * E + h * Dd;
    int tm = (tid >> 4) * 4, tn = (tid & 15) * 4;
    int row = tid >> 2;
    int k4  = (tid & 3) * 4;
    float acc[4][4] = {};

    for (int kt = 0; kt < Dd; kt += BK) {
        float4 a = *(const float4*)(Qb + (size_t)(m0 + row) * E + kt + k4);
        As[k4 + 0][row] = a.x; As[k4 + 1][row] = a.y;
        As[k4 + 2][row] = a.z; As[k4 + 3][row] = a.w;
        float4 bv = *(const float4*)(Kb + (size_t)(n0 + row) * E + kt + k4);
        Bs[k4 + 0][row] = bv.x; Bs[k4 + 1][row] = bv.y;
        Bs[k4 + 2][row] = bv.z; Bs[k4 + 3][row] = bv.w;
        __syncthreads();
#pragma unroll
        for (int kk = 0; kk < BK; kk++) {
            float a4[4], b4[4];
            *(float4*)a4 = *(const float4*)&As[kk][tm];
            *(float4*)b4 = *(const float4*)&Bs[kk][tn];
#pragma unroll
            for (int i = 0; i < 4; i++)
#pragma unroll
                for (int j = 0; j < 4; j++)
                    acc[i][j] += a4[i] * b4[j];
        }
        __syncthreads();
    }
    const float scale = 0.08838834764831845f;  // 1/sqrt(128)
#pragma unroll
    for (int i = 0; i < 4; i++) {
        float4 o = make_float4(acc[i][0] * scale, acc[i][1] * scale,
                               acc[i][2] * scale, acc[i][3] * scale);
        *(float4*)(attn + ((size_t)bh * Mm + m0 + tm + i) * Nn + n0 + tn) = o;
    }
}

// ---------------- softmax over n (warp per row of 256) ----------------
__global__ void __launch_bounds__(256) softmax_kernel(float* __restrict__ attn)
{
    int warp = threadIdx.x >> 5, lane = threadIdx.x & 31;
    size_t row = (size_t)blockIdx.x * 8 + warp;
    float4* p = (float4*)(attn + row * Nn);
    float4 v0 = p[lane];
    float4 v1 = p[lane + 32];
    float mx = fmaxf(fmaxf(fmaxf(v0.x, v0.y), fmaxf(v0.z, v0.w)),
                     fmaxf(fmaxf(v1.x, v1.y), fmaxf(v1.z, v1.w)));
#pragma unroll
    for (int o = 16; o; o >>= 1) mx = fmaxf(mx, __shfl_xor_sync(0xffffffffu, mx, o));
    v0.x = expf(v0.x - mx); v0.y = expf(v0.y - mx);
    v0.z = expf(v0.z - mx); v0.w = expf(v0.w - mx);
    v1.x = expf(v1.x - mx); v1.y = expf(v1.y - mx);
    v1.z = expf(v1.z - mx); v1.w = expf(v1.w - mx);
    float s = v0.x + v0.y + v0.z + v0.w + v1.x + v1.y + v1.z + v1.w;
#pragma unroll
    for (int o = 16; o; o >>= 1) s += __shfl_xor_sync(0xffffffffu, s, o);
    float inv = 1.f / s;
    v0.x *= inv; v0.y *= inv; v0.z *= inv; v0.w *= inv;
    v1.x *= inv; v1.y *= inv; v1.z *= inv; v1.w *= inv;
    p[lane] = v0;
    p[lane + 32] = v1;
}

// ---------------- O[b,m,h,d] = sum_n attn[b,h,m,n] * V[b,n,h,d] ----------------
__global__ void __launch_bounds__(256) attn_out(
    const float* __restrict__ attn, const float* __restrict__ V, float* __restrict__ O)
{
    const int BK = 16;
    __shared__ float As[BK][68];  // [n][m]
    __shared__ float Bs[BK][68];  // [n][d]
    int tid = threadIdx.x;
    int bh = blockIdx.z;
    int h = bh & (Hh - 1);
    int b = bh >> 5;
    int m0 = blockIdx.y * 64;
    int d0 = blockIdx.x * 64;
    const float* Ab = attn + (size_t)bh * Mm * Nn;
    const float* Vb = V + (size_t)b * Nn * E + h * Dd;
    int tm = (tid >> 4) * 4, tn = (tid & 15) * 4;
    int arow = tid >> 2, ak4 = (tid & 3) * 4;
    int bk = tid >> 4, bd4 = (tid & 15) * 4;
    float acc[4][4] = {};

    for (int kt = 0; kt < Nn; kt += BK) {
        float4 a = *(const float4*)(Ab + (size_t)(m0 + arow) * Nn + kt + ak4);
        As[ak4 + 0][arow] = a.x; As[ak4 + 1][arow] = a.y;
        As[ak4 + 2][arow] = a.z; As[ak4 + 3][arow] = a.w;
        float4 bv = *(const float4*)(Vb + (size_t)(kt + bk) * E + d0 + bd4);
        *(float4*)&Bs[bk][bd4] = bv;
        __syncthreads();
#pragma unroll
        for (int kk = 0; kk < BK; kk++) {
            float a4[4], b4[4];
            *(float4*)a4 = *(const float4*)&As[kk][tm];
            *(float4*)b4 = *(const float4*)&Bs[kk][tn];
#pragma unroll
            for (int i = 0; i < 4; i++)
#pragma unroll
                for (int j = 0; j < 4; j++)
                    acc[i][j] += a4[i] * b4[j];
        }
        __syncthreads();
    }
#pragma unroll
    for (int i = 0; i < 4; i++) {
        float4 o = make_float4(acc[i][0], acc[i][1], acc[i][2], acc[i][3]);
        *(float4*)(O + ((size_t)b * Mm + m0 + tm + i) * E + h * Dd + d0 + tn) = o;
    }
}

// ---------------- attn mean over heads ----------------
__global__ void __launch_bounds__(256) attn_mean_kernel(
    const float* __restrict__ attn, float* __restrict__ out)
{
    int idx = blockIdx.x * 256 + threadIdx.x;  // over B*M*N
    int b = idx / (Mm * Nn);
    int rem = idx - b * (Mm * Nn);
    const float* p = attn + (size_t)b * Hh * Mm * Nn + rem;
    float s = 0.f;
#pragma unroll
    for (int h = 0; h < Hh; h++) s += p[(size_t)h * Mm * Nn];
    out[idx] = s * (1.f / Hh);
}

// ---------------- launcher ----------------
extern "C" void kernel_launch(void* const* d_in, const int* in_sizes, int n_in,
                              void* d_out, int out_size)
{
    const float* x       = (const float*)d_in[0];
    const float* query   = (const float*)d_in[1];
    const float* pos     = (const float*)d_in[2];
    const float* ln_q_w  = (const float*)d_in[3];
    const float* ln_q_b  = (const float*)d_in[4];
    const float* ln_kv_w = (const float*)d_in[5];
    const float* ln_kv_b = (const float*)d_in[6];
    const float* in_w    = (const float*)d_in[7];
    const float* in_b    = (const float*)d_in[8];
    const float* out_w   = (const float*)d_in[9];
    const float* out_b   = (const float*)d_in[10];
    float* out = (float*)d_out;

    float *kv, *qin, *Qp, *Kp, *Vp, *Op, *attn;
    cudaGetSymbolAddress((void**)&kv,   g_kv);
    cudaGetSymbolAddress((void**)&qin,  g_qin);
    cudaGetSymbolAddress((void**)&Qp,   g_Q);
    cudaGetSymbolAddress((void**)&Kp,   g_K);
    cudaGetSymbolAddress((void**)&Vp,   g_V);
    cudaGetSymbolAddress((void**)&Op,   g_O);
    cudaGetSymbolAddress((void**)&attn, g_attn);

    cudaFuncSetAttribute(gemm_mma<false>, cudaFuncAttributeMaxDynamicSharedMemorySize, GEMM_SMEM_BYTES);
    cudaFuncSetAttribute(gemm_mma<true>,  cudaFuncAttributeMaxDynamicSharedMemorySize, GEMM_SMEM_BYTES);

    // 1) LayerNorms (q gets pos-embed fused)
    ln_kernel<<<Bb * Nn, 256>>>(x, ln_kv_w, ln_kv_b, nullptr, kv);
    ln_kernel<<<Mm, 256>>>(query, ln_q_w, ln_q_b, pos, qin);

    // 2) Projections on HMMA tensor cores (split-bf16 3-pass)
    gemm_mma<false><<<dim3(32, 2),  256, GEMM_SMEM_BYTES>>>(qin, in_w, in_b, nullptr, Qp);
    gemm_mma<true> <<<dim3(32, 16), 256, GEMM_SMEM_BYTES>>>(kv, in_w + (size_t)E * E, in_b + E, pos, Kp);
    gemm_mma<false><<<dim3(32, 16), 256, GEMM_SMEM_BYTES>>>(kv, in_w + (size_t)2 * E * E, in_b + 2 * E, nullptr, Vp);

    // 3) Attention (fp32 SIMT, unchanged this round)
    attn_score<<<dim3(4, 4, Bb * Hh), 256>>>(Qp, Kp, attn);
    softmax_kernel<<<Bb * Hh * Mm / 8, 256>>>(attn);
    attn_out<<<dim3(2, 4, Bb * Hh), 256>>>(attn, Vp, Op);

    // 4) Output projection -> d_out[0 : B*M*E)
    gemm_mma<false><<<dim3(32, 16), 256, GEMM_SMEM_BYTES>>>(Op, out_w, out_b, nullptr, out);

    // 5) attn.mean(heads) -> d_out[B*M*E : B*M*E + B*M*N)
    attn_mean_kernel<<<Bb * Mm * Nn / 256, 256>>>(attn, out + (size_t)Bb * Mm * E);
}

// round 4
// speedup vs baseline: 2.8171x; 1.4574x over previous
#include <cuda_runtime.h>
#include <cuda_bf16.h>
#include <cstdint>
#include <math.h>

#define E  4096
#define Hh 32
#define Mm 256
#define Bb 8
#define Nn 256
#define Dd 128

// ---------------- scratch (alloc-free: __device__ globals) ----------------
__device__ float g_Q[Mm * E];
__device__ float g_K[Bb * Nn * E];
__device__ float g_V[Bb * Nn * E];
__device__ float g_attn[Bb * Hh * Mm * Nn];

// bf16 hi/lo planes
__device__ __nv_bfloat16 g_qh[Mm * E],        g_ql[Mm * E];
__device__ __nv_bfloat16 g_kvh[Bb * Nn * E],  g_kvl[Bb * Nn * E];     // LN(x)
__device__ __nv_bfloat16 g_kvph[Bb * Nn * E], g_kvpl[Bb * Nn * E];    // LN(x)+pos
__device__ __nv_bfloat16 g_oh[Bb * Mm * E],   g_ol[Bb * Mm * E];      // attn output
__device__ __nv_bfloat16 g_wh[4ULL * E * E],  g_wl[4ULL * E * E];     // Wq,Wk,Wv,Wo

// ---------------- helpers ----------------
__device__ __forceinline__ uint32_t smem_u32(const void* p) {
    uint32_t a;
    asm("{ .reg .u64 t; cvta.to.shared.u64 t, %1; cvt.u32.u64 %0, t; }"
        : "=r"(a) : "l"(p));
    return a;
}

__device__ __forceinline__ void cp_async16(uint32_t dst, const void* src) {
    asm volatile("cp.async.cg.shared.global [%0], [%1], 16;"
                 :: "r"(dst), "l"(src) : "memory");
}
#define CP_COMMIT() asm volatile("cp.async.commit_group;" ::: "memory")
#define CP_WAIT1()  asm volatile("cp.async.wait_group 1;" ::: "memory")

__device__ __forceinline__ void mma16816(float* d, const uint32_t* a, const uint32_t* b) {
    asm volatile(
        "mma.sync.aligned.m16n8k16.row.col.f32.bf16.bf16.f32 "
        "{%0,%1,%2,%3}, {%4,%5,%6,%7}, {%8,%9}, {%0,%1,%2,%3};"
        : "+f"(d[0]), "+f"(d[1]), "+f"(d[2]), "+f"(d[3])
        : "r"(a[0]), "r"(a[1]), "r"(a[2]), "r"(a[3]), "r"(b[0]), "r"(b[1]));
}

__device__ __forceinline__ void split_f4(float4 v, uint2& hi, uint2& lo) {
    __nv_bfloat162 h0, h1, l0, l1;
    h0.x = __float2bfloat16_rn(v.x); h0.y = __float2bfloat16_rn(v.y);
    h1.x = __float2bfloat16_rn(v.z); h1.y = __float2bfloat16_rn(v.w);
    l0.x = __float2bfloat16_rn(v.x - __bfloat162float(h0.x));
    l0.y = __float2bfloat16_rn(v.y - __bfloat162float(h0.y));
    l1.x = __float2bfloat16_rn(v.z - __bfloat162float(h1.x));
    l1.y = __float2bfloat16_rn(v.w - __bfloat162float(h1.y));
    hi.x = *(uint32_t*)&h0; hi.y = *(uint32_t*)&h1;
    lo.x = *(uint32_t*)&l0; lo.y = *(uint32_t*)&l1;
}

// ---------------- fp32 -> bf16 hi/lo elementwise split ----------------
__global__ void __launch_bounds__(256) split_kernel(
    const float* __restrict__ src, __nv_bfloat16* __restrict__ hi,
    __nv_bfloat16* __restrict__ lo)
{
    size_t i = (size_t)blockIdx.x * 256 + threadIdx.x;
    float4 v = ((const float4*)src)[i];
    uint2 h, l;
    split_f4(v, h, l);
    *(uint2*)(hi + i * 4) = h;
    *(uint2*)(lo + i * 4) = l;
}

// ---------------- LayerNorm -> bf16 hi/lo planes (optionally +pos variant) ----------------
__global__ void __launch_bounds__(256) ln_split(
    const float* __restrict__ x, const float* __restrict__ w,
    const float* __restrict__ bias, const float* __restrict__ pos,
    __nv_bfloat16* __restrict__ h0, __nv_bfloat16* __restrict__ l0,
    __nv_bfloat16* __restrict__ hp, __nv_bfloat16* __restrict__ lp)
{
    int row = blockIdx.x;
    int tid = threadIdx.x;
    const float4* xr = (const float4*)(x + (size_t)row * E);
    float4 v[4];
    float s = 0.f, sq = 0.f;
#pragma unroll
    for (int i = 0; i < 4; i++) {
        v[i] = xr[tid + 256 * i];
        s  += v[i].x + v[i].y + v[i].z + v[i].w;
        sq += v[i].x * v[i].x + v[i].y * v[i].y + v[i].z * v[i].z + v[i].w * v[i].w;
    }
    __shared__ float s1[256], s2[256];
    s1[tid] = s; s2[tid] = sq;
    __syncthreads();
    for (int st = 128; st > 0; st >>= 1) {
        if (tid < st) { s1[tid] += s1[tid + st]; s2[tid] += s2[tid + st]; }
        __syncthreads();
    }
    float mean = s1[0] * (1.f / E);
    float var  = s2[0] * (1.f / E) - mean * mean;
    float rstd = rsqrtf(var + 1e-5f);

    const float4* wr = (const float4*)w;
    const float4* br = (const float4*)bias;
    const float4* pr = (const float4*)(pos + (size_t)(row & (Nn - 1)) * E);
#pragma unroll
    for (int i = 0; i < 4; i++) {
        int c = tid + 256 * i;
        float4 ww = wr[c], bb = br[c];
        float4 o;
        o.x = (v[i].x - mean) * rstd * ww.x + bb.x;
        o.y = (v[i].y - mean) * rstd * ww.y + bb.y;
        o.z = (v[i].z - mean) * rstd * ww.z + bb.z;
        o.w = (v[i].w - mean) * rstd * ww.w + bb.w;
        size_t off = (size_t)row * E + c * 4;
        uint2 h, l;
        if (h0) {
            split_f4(o, h, l);
            *(uint2*)(h0 + off) = h;
            *(uint2*)(l0 + off) = l;
        }
        if (hp) {
            float4 p = pr[c];
            o.x += p.x; o.y += p.y; o.z += p.z; o.w += p.w;
            split_f4(o, h, l);
            *(uint2*)(hp + off) = h;
            *(uint2*)(lp + off) = l;
        }
    }
}

// ======================= pipelined HMMA GEMM on bf16 planes =======================
// C(128x128) = (Ah+Al) @ (Wh+Wl)^T + bias, 3-pass split accum in fp32.
// BK=64, 3 stages, cp.async, 128B rows with XOR-8 chunk swizzle (conflict-free).
#define BK 64
#define PLANE_B 16384
#define STAGE_B (4 * PLANE_B)
#define GEMM_SMEM (3 * STAGE_B)

__device__ __forceinline__ uint32_t swo(int row, int col) {
    return (uint32_t)(row * 128 + (((col >> 3) ^ (row & 7)) << 4) + (col & 7) * 2);
}

__global__ void __launch_bounds__(256) gemm_pl(
    const __nv_bfloat16* __restrict__ Ahp, const __nv_bfloat16* __restrict__ Alp,
    const __nv_bfloat16* __restrict__ Whp, const __nv_bfloat16* __restrict__ Wlp,
    const float* __restrict__ bias, float* __restrict__ C)
{
    extern __shared__ char sm[];
    const uint32_t sbase = smem_u32(sm);
    const int tid  = threadIdx.x;
    const int wid  = tid >> 5;
    const int lane = tid & 31;
    const int g    = lane >> 2;
    const int tq   = lane & 3;
    const int wm   = (wid >> 1) * 32;
    const int wn   = (wid & 1) * 64;
    const int m0 = blockIdx.y * 128;
    const int n0 = blockIdx.x * 128;

    const __nv_bfloat16* p0 = Ahp + (size_t)m0 * E;
    const __nv_bfloat16* p1 = Alp + (size_t)m0 * E;
    const __nv_bfloat16* p2 = Whp + (size_t)n0 * E;
    const __nv_bfloat16* p3 = Wlp + (size_t)n0 * E;

    float acc[2][8][4];
#pragma unroll
    for (int i = 0; i < 2; i++)
#pragma unroll
        for (int j = 0; j < 8; j++)
#pragma unroll
            for (int k = 0; k < 4; k++) acc[i][j][k] = 0.f;

    const int NIT = E / BK;   // 64

    // issue loads for one stage slot
    auto issue = [&](int slot, int kt) {
        uint32_t sb = sbase + slot * STAGE_B;
#pragma unroll
        for (int j = 0; j < 16; j++) {
            const int plane = j >> 2;                 // 0:Ah 1:Al 2:Wh 3:Wl
            int idx = tid + 256 * (j & 3);            // 0..1023
            int row = idx >> 3;
            int c   = idx & 7;
            uint32_t dst = sb + plane * PLANE_B + row * 128 + ((c ^ (row & 7)) << 4);
            const __nv_bfloat16* src =
                (plane == 0 ? p0 : plane == 1 ? p1 : plane == 2 ? p2 : p3)
                + (size_t)row * E + kt + c * 8;
            cp_async16(dst, src);
        }
    };

    issue(0, 0);  CP_COMMIT();
    issue(1, BK); CP_COMMIT();

    for (int it = 0; it < NIT; it++) {
        CP_WAIT1();
        __syncthreads();
        if (it + 2 < NIT) issue((it + 2) % 3, (it + 2) * BK);
        CP_COMMIT();

        const char* base = sm + (it % 3) * STAGE_B;
        const char* Ahs = base;
        const char* Als = base + PLANE_B;
        const char* Bhs = base + 2 * PLANE_B;
        const char* Bls = base + 3 * PLANE_B;
#pragma unroll
        for (int ks = 0; ks < BK; ks += 16) {
            uint32_t ah[2][4], al[2][4], bf[8][2];
#pragma unroll
            for (int mt = 0; mt < 2; mt++)
#pragma unroll
                for (int r = 0; r < 4; r++) {
                    int row = wm + mt * 16 + g + (r & 1) * 8;
                    int col = ks + tq * 2 + (r >> 1) * 8;
                    ah[mt][r] = *(const uint32_t*)(Ahs + swo(row, col));
                    al[mt][r] = *(const uint32_t*)(Als + swo(row, col));
                }
#pragma unroll
            for (int nt = 0; nt < 8; nt++) {
                int row = wn + nt * 8 + g;
                bf[nt][0] = *(const uint32_t*)(Bhs + swo(row, ks + tq * 2));
                bf[nt][1] = *(const uint32_t*)(Bhs + swo(row, ks + tq * 2 + 8));
            }
#pragma unroll
            for (int mt = 0; mt < 2; mt++)
#pragma unroll
                for (int nt = 0; nt < 8; nt++) mma16816(acc[mt][nt], ah[mt], bf[nt]);
#pragma unroll
            for (int mt = 0; mt < 2; mt++)
#pragma unroll
                for (int nt = 0; nt < 8; nt++) mma16816(acc[mt][nt], al[mt], bf[nt]);
#pragma unroll
            for (int nt = 0; nt < 8; nt++) {
                int row = wn + nt * 8 + g;
                bf[nt][0] = *(const uint32_t*)(Bls + swo(row, ks + tq * 2));
                bf[nt][1] = *(const uint32_t*)(Bls + swo(row, ks + tq * 2 + 8));
            }
#pragma unroll
            for (int mt = 0; mt < 2; mt++)
#pragma unroll
                for (int nt = 0; nt < 8; nt++) mma16816(acc[mt][nt], ah[mt], bf[nt]);
        }
        __syncthreads();
    }

    // epilogue: bias + store fp32
    float bn[8][2];
#pragma unroll
    for (int nt = 0; nt < 8; nt++) {
        int n = n0 + wn + nt * 8 + tq * 2;
        bn[nt][0] = bias[n];
        bn[nt][1] = bias[n + 1];
    }
#pragma unroll
    for (int mt = 0; mt < 2; mt++)
#pragma unroll
        for (int half = 0; half < 2; half++) {
            int m = m0 + wm + mt * 16 + g + half * 8;
            float* cp = C + (size_t)m * E + n0 + wn;
#pragma unroll
            for (int nt = 0; nt < 8; nt++) {
                float2 v;
                v.x = acc[mt][nt][half * 2 + 0] + bn[nt][0];
                v.y = acc[mt][nt][half * 2 + 1] + bn[nt][1];
                *(float2*)(cp + nt * 8 + tq * 2) = v;
            }
        }
}

// ---------------- scores: S[b,h,m,n] = (Q_h[m,:] . K_bh[n,:]) / sqrt(D) ----------------
__global__ void __launch_bounds__(256) attn_score(
    const float* __restrict__ Q, const float* __restrict__ K, float* __restrict__ attn)
{
    const int BKs = 16;
    __shared__ float As[BKs][68];
    __shared__ float Bs[BKs][68];
    int tid = threadIdx.x;
    int bh = blockIdx.z;
    int hh = bh & (Hh - 1);
    int b = bh >> 5;
    int m0 = blockIdx.y * 64;
    int n0 = blockIdx.x * 64;
    const float* Qb = Q + hh * Dd;
    const float* Kb = K + (size_t)b * Nn * E + hh * Dd;
    int tm = (tid >> 4) * 4, tn = (tid & 15) * 4;
    int row = tid >> 2;
    int k4  = (tid & 3) * 4;
    float acc[4][4] = {};

    for (int kt = 0; kt < Dd; kt += BKs) {
        float4 a = *(const float4*)(Qb + (size_t)(m0 + row) * E + kt + k4);
        As[k4 + 0][row] = a.x; As[k4 + 1][row] = a.y;
        As[k4 + 2][row] = a.z; As[k4 + 3][row] = a.w;
        float4 bv = *(const float4*)(Kb + (size_t)(n0 + row) * E + kt + k4);
        Bs[k4 + 0][row] = bv.x; Bs[k4 + 1][row] = bv.y;
        Bs[k4 + 2][row] = bv.z; Bs[k4 + 3][row] = bv.w;
        __syncthreads();
#pragma unroll
        for (int kk = 0; kk < BKs; kk++) {
            float a4[4], b4[4];
            *(float4*)a4 = *(const float4*)&As[kk][tm];
            *(float4*)b4 = *(const float4*)&Bs[kk][tn];
#pragma unroll
            for (int i = 0; i < 4; i++)
#pragma unroll
                for (int j = 0; j < 4; j++)
                    acc[i][j] += a4[i] * b4[j];
        }
        __syncthreads();
    }
    const float scale = 0.08838834764831845f;  // 1/sqrt(128)
#pragma unroll
    for (int i = 0; i < 4; i++) {
        float4 o = make_float4(acc[i][0] * scale, acc[i][1] * scale,
                               acc[i][2] * scale, acc[i][3] * scale);
        *(float4*)(attn + ((size_t)bh * Mm + m0 + tm + i) * Nn + n0 + tn) = o;
    }
}

// ---------------- softmax over n (warp per row of 256) ----------------
__global__ void __launch_bounds__(256) softmax_kernel(float* __restrict__ attn)
{
    int warp = threadIdx.x >> 5, lane = threadIdx.x & 31;
    size_t row = (size_t)blockIdx.x * 8 + warp;
    float4* p = (float4*)(attn + row * Nn);
    float4 v0 = p[lane];
    float4 v1 = p[lane + 32];
    float mx = fmaxf(fmaxf(fmaxf(v0.x, v0.y), fmaxf(v0.z, v0.w)),
                     fmaxf(fmaxf(v1.x, v1.y), fmaxf(v1.z, v1.w)));
#pragma unroll
    for (int o = 16; o; o >>= 1) mx = fmaxf(mx, __shfl_xor_sync(0xffffffffu, mx, o));
    v0.x = expf(v0.x - mx); v0.y = expf(v0.y - mx);
    v0.z = expf(v0.z - mx); v0.w = expf(v0.w - mx);
    v1.x = expf(v1.x - mx); v1.y = expf(v1.y - mx);
    v1.z = expf(v1.z - mx); v1.w = expf(v1.w - mx);
    float s = v0.x + v0.y + v0.z + v0.w + v1.x + v1.y + v1.z + v1.w;
#pragma unroll
    for (int o = 16; o; o >>= 1) s += __shfl_xor_sync(0xffffffffu, s, o);
    float inv = 1.f / s;
    v0.x *= inv; v0.y *= inv; v0.z *= inv; v0.w *= inv;
    v1.x *= inv; v1.y *= inv; v1.z *= inv; v1.w *= inv;
    p[lane] = v0;
    p[lane + 32] = v1;
}

// ---------------- O[b,m,h,d] = sum_n attn * V ; writes bf16 hi/lo planes ----------------
__global__ void __launch_bounds__(256) attn_out(
    const float* __restrict__ attn, const float* __restrict__ V,
    __nv_bfloat16* __restrict__ Oh, __nv_bfloat16* __restrict__ Ol)
{
    const int BKs = 16;
    __shared__ float As[BKs][68];  // [n][m]
    __shared__ float Bs[BKs][68];  // [n][d]
    int tid = threadIdx.x;
    int bh = blockIdx.z;
    int hh = bh & (Hh - 1);
    int b = bh >> 5;
    int m0 = blockIdx.y * 64;
    int d0 = blockIdx.x * 64;
    const float* Ab = attn + (size_t)bh * Mm * Nn;
    const float* Vb = V + (size_t)b * Nn * E + hh * Dd;
    int tm = (tid >> 4) * 4, tn = (tid & 15) * 4;
    int arow = tid >> 2, ak4 = (tid & 3) * 4;
    int bk = tid >> 4, bd4 = (tid & 15) * 4;
    float acc[4][4] = {};

    for (int kt = 0; kt < Nn; kt += BKs) {
        float4 a = *(const float4*)(Ab + (size_t)(m0 + arow) * Nn + kt + ak4);
        As[ak4 + 0][arow] = a.x; As[ak4 + 1][arow] = a.y;
        As[ak4 + 2][arow] = a.z; As[ak4 + 3][arow] = a.w;
        float4 bv = *(const float4*)(Vb + (size_t)(kt + bk) * E + d0 + bd4);
        *(float4*)&Bs[bk][bd4] = bv;
        __syncthreads();
#pragma unroll
        for (int kk = 0; kk < BKs; kk++) {
            float a4[4], b4[4];
            *(float4*)a4 = *(const float4*)&As[kk][tm];
            *(float4*)b4 = *(const float4*)&Bs[kk][tn];
#pragma unroll
            for (int i = 0; i < 4; i++)
#pragma unroll
                for (int j = 0; j < 4; j++)
                    acc[i][j] += a4[i] * b4[j];
        }
        __syncthreads();
    }
#pragma unroll
    for (int i = 0; i < 4; i++) {
        float4 o = make_float4(acc[i][0], acc[i][1], acc[i][2], acc[i][3]);
        uint2 h, l;
        split_f4(o, h, l);
        size_t off = ((size_t)b * Mm + m0 + tm + i) * E + hh * Dd + d0 + tn;
        *(uint2*)(Oh + off) = h;
        *(uint2*)(Ol + off) = l;
    }
}

// ---------------- attn mean over heads ----------------
__global__ void __launch_bounds__(256) attn_mean_kernel(
    const float* __restrict__ attn, float* __restrict__ out)
{
    int idx = blockIdx.x * 256 + threadIdx.x;  // over B*M*N
    int b = idx / (Mm * Nn);
    int rem = idx - b * (Mm * Nn);
    const float* p = attn + (size_t)b * Hh * Mm * Nn + rem;
    float s = 0.f;
#pragma unroll
    for (int h = 0; h < Hh; h++) s += p[(size_t)h * Mm * Nn];
    out[idx] = s * (1.f / Hh);
}

// ---------------- launcher ----------------
extern "C" void kernel_launch(void* const* d_in, const int* in_sizes, int n_in,
                              void* d_out, int out_size)
{
    const float* x       = (const float*)d_in[0];
    const float* query   = (const float*)d_in[1];
    const float* pos     = (const float*)d_in[2];
    const float* ln_q_w  = (const float*)d_in[3];
    const float* ln_q_b  = (const float*)d_in[4];
    const float* ln_kv_w = (const float*)d_in[5];
    const float* ln_kv_b = (const float*)d_in[6];
    const float* in_w    = (const float*)d_in[7];
    const float* in_b    = (const float*)d_in[8];
    const float* out_w   = (const float*)d_in[9];
    const float* out_b   = (const float*)d_in[10];
    float* out = (float*)d_out;

    float *Qp, *Kp, *Vp, *attn;
    cudaGetSymbolAddress((void**)&Qp,   g_Q);
    cudaGetSymbolAddress((void**)&Kp,   g_K);
    cudaGetSymbolAddress((void**)&Vp,   g_V);
    cudaGetSymbolAddress((void**)&attn, g_attn);
    __nv_bfloat16 *qh, *ql, *kvh, *kvl, *kvph, *kvpl, *oh, *ol, *wh, *wl;
    cudaGetSymbolAddress((void**)&qh,   g_qh);
    cudaGetSymbolAddress((void**)&ql,   g_ql);
    cudaGetSymbolAddress((void**)&kvh,  g_kvh);
    cudaGetSymbolAddress((void**)&kvl,  g_kvl);
    cudaGetSymbolAddress((void**)&kvph, g_kvph);
    cudaGetSymbolAddress((void**)&kvpl, g_kvpl);
    cudaGetSymbolAddress((void**)&oh,   g_oh);
    cudaGetSymbolAddress((void**)&ol,   g_ol);
    cudaGetSymbolAddress((void**)&wh,   g_wh);
    cudaGetSymbolAddress((void**)&wl,   g_wl);

    cudaFuncSetAttribute(gemm_pl, cudaFuncAttributeMaxDynamicSharedMemorySize, GEMM_SMEM);

    // 0) split weights into bf16 hi/lo planes
    split_kernel<<<(3ULL * E * E / 4) / 256, 256>>>(in_w, wh, wl);
    split_kernel<<<((size_t)E * E / 4) / 256, 256>>>(out_w, wh + 3ULL * E * E, wl + 3ULL * E * E);

    // 1) LayerNorms -> bf16 hi/lo planes (kv: plain + pos variants; q: pos only)
    ln_split<<<Bb * Nn, 256>>>(x, ln_kv_w, ln_kv_b, pos, kvh, kvl, kvph, kvpl);
    ln_split<<<Mm, 256>>>(query, ln_q_w, ln_q_b, pos, nullptr, nullptr, qh, ql);

    // 2) Projections (pipelined HMMA)
    gemm_pl<<<dim3(32, 2),  256, GEMM_SMEM>>>(qh,   ql,   wh,                wl,                in_b,         Qp);
    gemm_pl<<<dim3(32, 16), 256, GEMM_SMEM>>>(kvph, kvpl, wh + (size_t)E * E, wl + (size_t)E * E, in_b + E,     Kp);
    gemm_pl<<<dim3(32, 16), 256, GEMM_SMEM>>>(kvh,  kvl,  wh + 2ULL * E * E, wl + 2ULL * E * E, in_b + 2 * E, Vp);

    // 3) Attention
    attn_score<<<dim3(4, 4, Bb * Hh), 256>>>(Qp, Kp, attn);
    softmax_kernel<<<Bb * Hh * Mm / 8, 256>>>(attn);
    attn_out<<<dim3(2, 4, Bb * Hh), 256>>>(attn, Vp, oh, ol);

    // 4) Output projection -> d_out[0 : B*M*E)
    gemm_pl<<<dim3(32, 16), 256, GEMM_SMEM>>>(oh, ol, wh + 3ULL * E * E, wl + 3ULL * E * E, out_b, out);

    // 5) attn.mean(heads) -> d_out[B*M*E : B*M*E + B*M*N)
    attn_mean_kernel<<<Bb * Mm * Nn / 256, 256>>>(attn, out + (size_t)Bb * Mm * E);
}

// round 5
// speedup vs baseline: 2.9111x; 1.0334x over previous
#include <cuda_runtime.h>
#include <cuda_bf16.h>
#include <cstdint>
#include <math.h>

#define E  4096
#define Hh 32
#define Mm 256
#define Bb 8
#define Nn 256
#define Dd 128

// ---------------- scratch (alloc-free: __device__ globals) ----------------
__device__ float g_attn[Bb * Hh * Mm * Nn];

// bf16 hi/lo planes
__device__ __nv_bfloat16 g_qh[Mm * E],        g_ql[Mm * E];           // LN(query)+pos
__device__ __nv_bfloat16 g_kvh[Bb * Nn * E],  g_kvl[Bb * Nn * E];     // LN(x)
__device__ __nv_bfloat16 g_kvph[Bb * Nn * E], g_kvpl[Bb * Nn * E];    // LN(x)+pos
__device__ __nv_bfloat16 g_Qh[Mm * E],        g_Ql[Mm * E];           // Q proj
__device__ __nv_bfloat16 g_Kh[Bb * Nn * E],   g_Kl[Bb * Nn * E];      // K proj
__device__ __nv_bfloat16 g_Vh[Bb * Nn * E],   g_Vl[Bb * Nn * E];      // V proj
__device__ __nv_bfloat16 g_Vth[Bb * Hh * Dd * Nn], g_Vtl[Bb * Hh * Dd * Nn]; // V^T per (b,h)
__device__ __nv_bfloat16 g_Ph[Bb * Hh * Mm * Nn],  g_Pl[Bb * Hh * Mm * Nn];  // softmax planes
__device__ __nv_bfloat16 g_oh[Bb * Mm * E],   g_ol[Bb * Mm * E];      // attn output
__device__ __nv_bfloat16 g_wh[4ULL * E * E],  g_wl[4ULL * E * E];     // Wq,Wk,Wv,Wo

// ---------------- helpers ----------------
__device__ __forceinline__ uint32_t smem_u32(const void* p) {
    uint32_t a;
    asm("{ .reg .u64 t; cvta.to.shared.u64 t, %1; cvt.u32.u64 %0, t; }"
        : "=r"(a) : "l"(p));
    return a;
}

__device__ __forceinline__ void cp_async16(uint32_t dst, const void* src) {
    asm volatile("cp.async.cg.shared.global [%0], [%1], 16;"
                 :: "r"(dst), "l"(src) : "memory");
}
#define CP_COMMIT() asm volatile("cp.async.commit_group;" ::: "memory")
#define CP_WAIT1()  asm volatile("cp.async.wait_group 1;" ::: "memory")

__device__ __forceinline__ void mma16816(float* d, const uint32_t* a, const uint32_t* b) {
    asm volatile(
        "mma.sync.aligned.m16n8k16.row.col.f32.bf16.bf16.f32 "
        "{%0,%1,%2,%3}, {%4,%5,%6,%7}, {%8,%9}, {%0,%1,%2,%3};"
        : "+f"(d[0]), "+f"(d[1]), "+f"(d[2]), "+f"(d[3])
        : "r"(a[0]), "r"(a[1]), "r"(a[2]), "r"(a[3]), "r"(b[0]), "r"(b[1]));
}

__device__ __forceinline__ void split_f4(float4 v, uint2& hi, uint2& lo) {
    __nv_bfloat162 h0, h1, l0, l1;
    h0.x = __float2bfloat16_rn(v.x); h0.y = __float2bfloat16_rn(v.y);
    h1.x = __float2bfloat16_rn(v.z); h1.y = __float2bfloat16_rn(v.w);
    l0.x = __float2bfloat16_rn(v.x - __bfloat162float(h0.x));
    l0.y = __float2bfloat16_rn(v.y - __bfloat162float(h0.y));
    l1.x = __float2bfloat16_rn(v.z - __bfloat162float(h1.x));
    l1.y = __float2bfloat16_rn(v.w - __bfloat162float(h1.y));
    hi.x = *(uint32_t*)&h0; hi.y = *(uint32_t*)&h1;
    lo.x = *(uint32_t*)&l0; lo.y = *(uint32_t*)&l1;
}

__device__ __forceinline__ void split2(float x, float y, uint32_t& h, uint32_t& l) {
    __nv_bfloat162 hh, ll;
    hh.x = __float2bfloat16_rn(x); hh.y = __float2bfloat16_rn(y);
    ll.x = __float2bfloat16_rn(x - __bfloat162float(hh.x));
    ll.y = __float2bfloat16_rn(y - __bfloat162float(hh.y));
    h = *(uint32_t*)&hh; l = *(uint32_t*)&ll;
}

// ---------------- fp32 -> bf16 hi/lo elementwise split ----------------
__global__ void __launch_bounds__(256) split_kernel(
    const float* __restrict__ src, __nv_bfloat16* __restrict__ hi,
    __nv_bfloat16* __restrict__ lo)
{
    size_t i = (size_t)blockIdx.x * 256 + threadIdx.x;
    float4 v = ((const float4*)src)[i];
    uint2 h, l;
    split_f4(v, h, l);
    *(uint2*)(hi + i * 4) = h;
    *(uint2*)(lo + i * 4) = l;
}

// ---------------- LayerNorm -> bf16 hi/lo planes (plain and/or +pos) ----------------
__global__ void __launch_bounds__(256) ln_split(
    const float* __restrict__ x, const float* __restrict__ w,
    const float* __restrict__ bias, const float* __restrict__ pos,
    __nv_bfloat16* __restrict__ h0, __nv_bfloat16* __restrict__ l0,
    __nv_bfloat16* __restrict__ hp, __nv_bfloat16* __restrict__ lp)
{
    int row = blockIdx.x;
    int tid = threadIdx.x;
    const float4* xr = (const float4*)(x + (size_t)row * E);
    float4 v[4];
    float s = 0.f, sq = 0.f;
#pragma unroll
    for (int i = 0; i < 4; i++) {
        v[i] = xr[tid + 256 * i];
        s  += v[i].x + v[i].y + v[i].z + v[i].w;
        sq += v[i].x * v[i].x + v[i].y * v[i].y + v[i].z * v[i].z + v[i].w * v[i].w;
    }
    __shared__ float s1[256], s2[256];
    s1[tid] = s; s2[tid] = sq;
    __syncthreads();
    for (int st = 128; st > 0; st >>= 1) {
        if (tid < st) { s1[tid] += s1[tid + st]; s2[tid] += s2[tid + st]; }
        __syncthreads();
    }
    float mean = s1[0] * (1.f / E);
    float var  = s2[0] * (1.f / E) - mean * mean;
    float rstd = rsqrtf(var + 1e-5f);

    const float4* wr = (const float4*)w;
    const float4* br = (const float4*)bias;
    const float4* pr = (const float4*)(pos + (size_t)(row & (Nn - 1)) * E);
#pragma unroll
    for (int i = 0; i < 4; i++) {
        int c = tid + 256 * i;
        float4 ww = wr[c], bb = br[c];
        float4 o;
        o.x = (v[i].x - mean) * rstd * ww.x + bb.x;
        o.y = (v[i].y - mean) * rstd * ww.y + bb.y;
        o.z = (v[i].z - mean) * rstd * ww.z + bb.z;
        o.w = (v[i].w - mean) * rstd * ww.w + bb.w;
        size_t off = (size_t)row * E + c * 4;
        uint2 h, l;
        if (h0) {
            split_f4(o, h, l);
            *(uint2*)(h0 + off) = h;
            *(uint2*)(l0 + off) = l;
        }
        if (hp) {
            float4 p = pr[c];
            o.x += p.x; o.y += p.y; o.z += p.z; o.w += p.w;
            split_f4(o, h, l);
            *(uint2*)(hp + off) = h;
            *(uint2*)(lp + off) = l;
        }
    }
}

// ======================= universal pipelined HMMA GEMM =======================
// C(128x128 tile) = scale*((Ah+Al)@(Bh+Bl)^T) [+ bias], 3-pass split, fp32 accum.
// Batched via blockIdx.z (z = b*32 + h): ptr += h*SH + b*SB per operand.
// Output: fp32 (Cf) and/or bf16 hi/lo planes (Ch/Cl).
#define BK 64
#define PLANE_B 16384
#define STAGE_B (4 * PLANE_B)
#define GEMM_SMEM (3 * STAGE_B)

__device__ __forceinline__ uint32_t swo(int row, int col) {
    return (uint32_t)(row * 128 + (((col >> 3) ^ (row & 7)) << 4) + (col & 7) * 2);
}

__global__ void __launch_bounds__(256) gemm_u(
    const __nv_bfloat16* __restrict__ Ahp, const __nv_bfloat16* __restrict__ Alp,
    const __nv_bfloat16* __restrict__ Bhp, const __nv_bfloat16* __restrict__ Blp,
    const float* __restrict__ bias, float scale,
    float* __restrict__ Cf,
    __nv_bfloat16* __restrict__ Ch, __nv_bfloat16* __restrict__ Cl,
    size_t aSH, size_t aSB, size_t bSH, size_t bSB, size_t cSH, size_t cSB,
    int lda, int ldb, int ldc, int NIT)
{
    extern __shared__ char sm[];
    const uint32_t sbase = smem_u32(sm);
    const int tid  = threadIdx.x;
    const int wid  = tid >> 5;
    const int lane = tid & 31;
    const int g    = lane >> 2;
    const int tq   = lane & 3;
    const int wm   = (wid >> 1) * 32;
    const int wn   = (wid & 1) * 64;
    const int m0 = blockIdx.y * 128;
    const int n0 = blockIdx.x * 128;
    const int z  = blockIdx.z;
    const int hz = z & 31, bz = z >> 5;
    const size_t aOff = (size_t)hz * aSH + (size_t)bz * aSB;
    const size_t bOff = (size_t)hz * bSH + (size_t)bz * bSB;
    const size_t cOff = (size_t)hz * cSH + (size_t)bz * cSB;

    const __nv_bfloat16* p0 = Ahp + aOff + (size_t)m0 * lda;
    const __nv_bfloat16* p1 = Alp + aOff + (size_t)m0 * lda;
    const __nv_bfloat16* p2 = Bhp + bOff + (size_t)n0 * ldb;
    const __nv_bfloat16* p3 = Blp + bOff + (size_t)n0 * ldb;

    float acc[2][8][4];
#pragma unroll
    for (int i = 0; i < 2; i++)
#pragma unroll
        for (int j = 0; j < 8; j++)
#pragma unroll
            for (int k = 0; k < 4; k++) acc[i][j][k] = 0.f;

    auto issue = [&](int slot, int kt) {
        uint32_t sb = sbase + slot * STAGE_B;
#pragma unroll
        for (int j = 0; j < 16; j++) {
            const int plane = j >> 2;
            int idx = tid + 256 * (j & 3);
            int row = idx >> 3;
            int c   = idx & 7;
            uint32_t dst = sb + plane * PLANE_B + row * 128 + ((c ^ (row & 7)) << 4);
            const __nv_bfloat16* src =
                (plane == 0 ? p0 : plane == 1 ? p1 : plane == 2 ? p2 : p3)
                + (size_t)row * (plane < 2 ? lda : ldb) + kt + c * 8;
            cp_async16(dst, src);
        }
    };

    issue(0, 0);  CP_COMMIT();
    issue(1, BK); CP_COMMIT();

    for (int it = 0; it < NIT; it++) {
        CP_WAIT1();
        __syncthreads();
        if (it + 2 < NIT) issue((it + 2) % 3, (it + 2) * BK);
        CP_COMMIT();

        const char* base = sm + (it % 3) * STAGE_B;
        const char* Ahs = base;
        const char* Als = base + PLANE_B;
        const char* Bhs = base + 2 * PLANE_B;
        const char* Bls = base + 3 * PLANE_B;
#pragma unroll
        for (int ks = 0; ks < BK; ks += 16) {
            uint32_t ah[2][4], al[2][4], bf[8][2];
#pragma unroll
            for (int mt = 0; mt < 2; mt++)
#pragma unroll
                for (int r = 0; r < 4; r++) {
                    int row = wm + mt * 16 + g + (r & 1) * 8;
                    int col = ks + tq * 2 + (r >> 1) * 8;
                    ah[mt][r] = *(const uint32_t*)(Ahs + swo(row, col));
                    al[mt][r] = *(const uint32_t*)(Als + swo(row, col));
                }
#pragma unroll
            for (int nt = 0; nt < 8; nt++) {
                int row = wn + nt * 8 + g;
                bf[nt][0] = *(const uint32_t*)(Bhs + swo(row, ks + tq * 2));
                bf[nt][1] = *(const uint32_t*)(Bhs + swo(row, ks + tq * 2 + 8));
            }
#pragma unroll
            for (int mt = 0; mt < 2; mt++)
#pragma unroll
                for (int nt = 0; nt < 8; nt++) mma16816(acc[mt][nt], ah[mt], bf[nt]);
#pragma unroll
            for (int mt = 0; mt < 2; mt++)
#pragma unroll
                for (int nt = 0; nt < 8; nt++) mma16816(acc[mt][nt], al[mt], bf[nt]);
#pragma unroll
            for (int nt = 0; nt < 8; nt++) {
                int row = wn + nt * 8 + g;
                bf[nt][0] = *(const uint32_t*)(Bls + swo(row, ks + tq * 2));
                bf[nt][1] = *(const uint32_t*)(Bls + swo(row, ks + tq * 2 + 8));
            }
#pragma unroll
            for (int mt = 0; mt < 2; mt++)
#pragma unroll
                for (int nt = 0; nt < 8; nt++) mma16816(acc[mt][nt], ah[mt], bf[nt]);
        }
        __syncthreads();
    }

    // epilogue
    float bn[8][2];
#pragma unroll
    for (int nt = 0; nt < 8; nt++) {
        if (bias) {
            int n = n0 + wn + nt * 8 + tq * 2;
            bn[nt][0] = bias[n];
            bn[nt][1] = bias[n + 1];
        } else {
            bn[nt][0] = 0.f; bn[nt][1] = 0.f;
        }
    }
#pragma unroll
    for (int mt = 0; mt < 2; mt++)
#pragma unroll
        for (int half = 0; half < 2; half++) {
            int m = m0 + wm + mt * 16 + g + half * 8;
#pragma unroll
            for (int nt = 0; nt < 8; nt++) {
                float vx = acc[mt][nt][half * 2 + 0] * scale + bn[nt][0];
                float vy = acc[mt][nt][half * 2 + 1] * scale + bn[nt][1];
                size_t off = cOff + (size_t)m * ldc + n0 + wn + nt * 8 + tq * 2;
                if (Cf) *(float2*)(Cf + off) = make_float2(vx, vy);
                if (Ch) {
                    uint32_t h, l;
                    split2(vx, vy, h, l);
                    *(uint32_t*)(Ch + off) = h;
                    *(uint32_t*)(Cl + off) = l;
                }
            }
        }
}

// ---------------- V planes -> V^T planes per (b,h): [n][d] -> [d][n] ----------------
__global__ void __launch_bounds__(256) vtrans(
    const __nv_bfloat16* __restrict__ Vh, const __nv_bfloat16* __restrict__ Vl,
    __nv_bfloat16* __restrict__ Vth, __nv_bfloat16* __restrict__ Vtl)
{
    __shared__ __nv_bfloat16 t0[32][33], t1[32][33];
    int z = blockIdx.z;
    int hz = z & 31, bz = z >> 5;
    int d0 = blockIdx.x * 32;
    int n0 = blockIdx.y * 32;
    int tx = threadIdx.x & 31, ty = threadIdx.x >> 5;   // 32 x 8
#pragma unroll
    for (int i = 0; i < 4; i++) {
        int n = n0 + ty + i * 8;
        size_t src = ((size_t)bz * Nn + n) * E + hz * Dd + d0 + tx;
        t0[ty + i * 8][tx] = Vh[src];
        t1[ty + i * 8][tx] = Vl[src];
    }
    __syncthreads();
#pragma unroll
    for (int i = 0; i < 4; i++) {
        int d = d0 + ty + i * 8;
        size_t dst = ((size_t)z * Dd + d) * Nn + n0 + tx;
        Vth[dst] = t0[tx][ty + i * 8];
        Vtl[dst] = t1[tx][ty + i * 8];
    }
}

// ---------------- softmax over n; writes fp32 in-place + bf16 hi/lo planes ----------------
__global__ void __launch_bounds__(256) softmax_kernel(
    float* __restrict__ attn,
    __nv_bfloat16* __restrict__ Ph, __nv_bfloat16* __restrict__ Pl)
{
    int warp = threadIdx.x >> 5, lane = threadIdx.x & 31;
    size_t row = (size_t)blockIdx.x * 8 + warp;
    float4* p = (float4*)(attn + row * Nn);
    float4 v0 = p[lane];
    float4 v1 = p[lane + 32];
    float mx = fmaxf(fmaxf(fmaxf(v0.x, v0.y), fmaxf(v0.z, v0.w)),
                     fmaxf(fmaxf(v1.x, v1.y), fmaxf(v1.z, v1.w)));
#pragma unroll
    for (int o = 16; o; o >>= 1) mx = fmaxf(mx, __shfl_xor_sync(0xffffffffu, mx, o));
    v0.x = expf(v0.x - mx); v0.y = expf(v0.y - mx);
    v0.z = expf(v0.z - mx); v0.w = expf(v0.w - mx);
    v1.x = expf(v1.x - mx); v1.y = expf(v1.y - mx);
    v1.z = expf(v1.z - mx); v1.w = expf(v1.w - mx);
    float s = v0.x + v0.y + v0.z + v0.w + v1.x + v1.y + v1.z + v1.w;
#pragma unroll
    for (int o = 16; o; o >>= 1) s += __shfl_xor_sync(0xffffffffu, s, o);
    float inv = 1.f / s;
    v0.x *= inv; v0.y *= inv; v0.z *= inv; v0.w *= inv;
    v1.x *= inv; v1.y *= inv; v1.z *= inv; v1.w *= inv;
    p[lane] = v0;
    p[lane + 32] = v1;
    uint2 h, l;
    split_f4(v0, h, l);
    *(uint2*)(Ph + row * Nn + lane * 4) = h;
    *(uint2*)(Pl + row * Nn + lane * 4) = l;
    split_f4(v1, h, l);
    *(uint2*)(Ph + row * Nn + 128 + lane * 4) = h;
    *(uint2*)(Pl + row * Nn + 128 + lane * 4) = l;
}

// ---------------- attn mean over heads ----------------
__global__ void __launch_bounds__(256) attn_mean_kernel(
    const float* __restrict__ attn, float* __restrict__ out)
{
    int idx = blockIdx.x * 256 + threadIdx.x;
    int b = idx / (Mm * Nn);
    int rem = idx - b * (Mm * Nn);
    const float* p = attn + (size_t)b * Hh * Mm * Nn + rem;
    float s = 0.f;
#pragma unroll
    for (int h = 0; h < Hh; h++) s += p[(size_t)h * Mm * Nn];
    out[idx] = s * (1.f / Hh);
}

// ---------------- launcher ----------------
extern "C" void kernel_launch(void* const* d_in, const int* in_sizes, int n_in,
                              void* d_out, int out_size)
{
    const float* x       = (const float*)d_in[0];
    const float* query   = (const float*)d_in[1];
    const float* pos     = (const float*)d_in[2];
    const float* ln_q_w  = (const float*)d_in[3];
    const float* ln_q_b  = (const float*)d_in[4];
    const float* ln_kv_w = (const float*)d_in[5];
    const float* ln_kv_b = (const float*)d_in[6];
    const float* in_w    = (const float*)d_in[7];
    const float* in_b    = (const float*)d_in[8];
    const float* out_w   = (const float*)d_in[9];
    const float* out_b   = (const float*)d_in[10];
    float* out = (float*)d_out;

    float *attn;
    cudaGetSymbolAddress((void**)&attn, g_attn);
    __nv_bfloat16 *qh, *ql, *kvh, *kvl, *kvph, *kvpl;
    __nv_bfloat16 *Qh, *Ql, *Kh, *Kl, *Vh, *Vl, *Vth, *Vtl, *Ph, *Pl, *oh, *ol, *wh, *wl;
    cudaGetSymbolAddress((void**)&qh,   g_qh);
    cudaGetSymbolAddress((void**)&ql,   g_ql);
    cudaGetSymbolAddress((void**)&kvh,  g_kvh);
    cudaGetSymbolAddress((void**)&kvl,  g_kvl);
    cudaGetSymbolAddress((void**)&kvph, g_kvph);
    cudaGetSymbolAddress((void**)&kvpl, g_kvpl);
    cudaGetSymbolAddress((void**)&Qh,   g_Qh);
    cudaGetSymbolAddress((void**)&Ql,   g_Ql);
    cudaGetSymbolAddress((void**)&Kh,   g_Kh);
    cudaGetSymbolAddress((void**)&Kl,   g_Kl);
    cudaGetSymbolAddress((void**)&Vh,   g_Vh);
    cudaGetSymbolAddress((void**)&Vl,   g_Vl);
    cudaGetSymbolAddress((void**)&Vth,  g_Vth);
    cudaGetSymbolAddress((void**)&Vtl,  g_Vtl);
    cudaGetSymbolAddress((void**)&Ph,   g_Ph);
    cudaGetSymbolAddress((void**)&Pl,   g_Pl);
    cudaGetSymbolAddress((void**)&oh,   g_oh);
    cudaGetSymbolAddress((void**)&ol,   g_ol);
    cudaGetSymbolAddress((void**)&wh,   g_wh);
    cudaGetSymbolAddress((void**)&wl,   g_wl);

    cudaFuncSetAttribute(gemm_u, cudaFuncAttributeMaxDynamicSharedMemorySize, GEMM_SMEM);

    // 0) split weights
    split_kernel<<<(3ULL * E * E / 4) / 256, 256>>>(in_w, wh, wl);
    split_kernel<<<((size_t)E * E / 4) / 256, 256>>>(out_w, wh + 3ULL * E * E, wl + 3ULL * E * E);

    // 1) LayerNorms -> split planes
    ln_split<<<Bb * Nn, 256>>>(x, ln_kv_w, ln_kv_b, pos, kvh, kvl, kvph, kvpl);
    ln_split<<<Mm, 256>>>(query, ln_q_w, ln_q_b, pos, nullptr, nullptr, qh, ql);

    // 2) Projections -> split planes directly
    gemm_u<<<dim3(32, 2, 1), 256, GEMM_SMEM>>>(
        qh, ql, wh, wl, in_b, 1.f, nullptr, Qh, Ql,
        0, 0, 0, 0, 0, 0, E, E, E, E / BK);
    gemm_u<<<dim3(32, 16, 1), 256, GEMM_SMEM>>>(
        kvph, kvpl, wh + (size_t)E * E, wl + (size_t)E * E, in_b + E, 1.f, nullptr, Kh, Kl,
        0, 0, 0, 0, 0, 0, E, E, E, E / BK);
    gemm_u<<<dim3(32, 16, 1), 256, GEMM_SMEM>>>(
        kvh, kvl, wh + 2ULL * E * E, wl + 2ULL * E * E, in_b + 2 * E, 1.f, nullptr, Vh, Vl,
        0, 0, 0, 0, 0, 0, E, E, E, E / BK);

    // 3) V transpose -> [bh][d][n]
    vtrans<<<dim3(Dd / 32, Nn / 32, Bb * Hh), 256>>>(Vh, Vl, Vth, Vtl);

    // 4) scores = Q @ K^T / sqrt(D)   (batched over bh)
    gemm_u<<<dim3(2, 2, Bb * Hh), 256, GEMM_SMEM>>>(
        Qh, Ql, Kh, Kl, nullptr, 0.08838834764831845f, attn, nullptr, nullptr,
        (size_t)Dd, 0, (size_t)Dd, (size_t)Nn * E,
        (size_t)Mm * Nn, 32ULL * Mm * Nn, E, E, Nn, Dd / BK);

    // 5) softmax (+ P planes)
    softmax_kernel<<<Bb * Hh * Mm / 8, 256>>>(attn, Ph, Pl);

    // 6) O = P @ V   (batched over bh) -> O split planes
    gemm_u<<<dim3(1, 2, Bb * Hh), 256, GEMM_SMEM>>>(
        Ph, Pl, Vth, Vtl, nullptr, 1.f, nullptr, oh, ol,
        (size_t)Mm * Nn, 32ULL * Mm * Nn, (size_t)Dd * Nn, 32ULL * Dd * Nn,
        (size_t)Dd, (size_t)Mm * E, Nn, Nn, E, Nn / BK);

    // 7) out projection -> d_out
    gemm_u<<<dim3(32, 16, 1), 256, GEMM_SMEM>>>(
        oh, ol, wh + 3ULL * E * E, wl + 3ULL * E * E, out_b, 1.f, out, nullptr, nullptr,
        0, 0, 0, 0, 0, 0, E, E, E, E / BK);

    // 8) attn.mean(heads)
    attn_mean_kernel<<<Bb * Mm * Nn / 256, 256>>>(attn, out + (size_t)Bb * Mm * E);
}

// round 6
// speedup vs baseline: 2.9573x; 1.0159x over previous
#include <cuda_runtime.h>
#include <cuda_bf16.h>
#include <cstdint>
#include <math.h>

#define E  4096
#define Hh 32
#define Mm 256
#define Bb 8
#define Nn 256
#define Dd 128

// ---------------- scratch (alloc-free: __device__ globals) ----------------
__device__ float g_attn[Bb * Hh * Mm * Nn];

// bf16 hi/lo planes
__device__ __nv_bfloat16 g_qh[Mm * E],        g_ql[Mm * E];           // LN(query)+pos
__device__ __nv_bfloat16 g_kvh[Bb * Nn * E],  g_kvl[Bb * Nn * E];     // LN(x)
__device__ __nv_bfloat16 g_kvph[Bb * Nn * E], g_kvpl[Bb * Nn * E];    // LN(x)+pos
__device__ __nv_bfloat16 g_Qh[Mm * E],        g_Ql[Mm * E];           // Q proj
__device__ __nv_bfloat16 g_Kh[Bb * Nn * E],   g_Kl[Bb * Nn * E];      // K proj
__device__ __nv_bfloat16 g_Vh[Bb * Nn * E],   g_Vl[Bb * Nn * E];      // V proj
__device__ __nv_bfloat16 g_Vth[Bb * Hh * Dd * Nn], g_Vtl[Bb * Hh * Dd * Nn]; // V^T per (b,h)
__device__ __nv_bfloat16 g_Ph[Bb * Hh * Mm * Nn],  g_Pl[Bb * Hh * Mm * Nn];  // softmax planes
__device__ __nv_bfloat16 g_oh[Bb * Mm * E],   g_ol[Bb * Mm * E];      // attn output
__device__ __nv_bfloat16 g_wh[4ULL * E * E],  g_wl[4ULL * E * E];     // Wq,Wk,Wv,Wo

// ---------------- helpers ----------------
__device__ __forceinline__ uint32_t smem_u32(const void* p) {
    uint32_t a;
    asm("{ .reg .u64 t; cvta.to.shared.u64 t, %1; cvt.u32.u64 %0, t; }"
        : "=r"(a) : "l"(p));
    return a;
}

__device__ __forceinline__ void cp_async16(uint32_t dst, const void* src) {
    asm volatile("cp.async.cg.shared.global [%0], [%1], 16;"
                 :: "r"(dst), "l"(src) : "memory");
}
#define CP_COMMIT() asm volatile("cp.async.commit_group;" ::: "memory")
#define CP_WAIT1()  asm volatile("cp.async.wait_group 1;" ::: "memory")

__device__ __forceinline__ void mma16816(float* d, const uint32_t* a, const uint32_t* b) {
    asm volatile(
        "mma.sync.aligned.m16n8k16.row.col.f32.bf16.bf16.f32 "
        "{%0,%1,%2,%3}, {%4,%5,%6,%7}, {%8,%9}, {%0,%1,%2,%3};"
        : "+f"(d[0]), "+f"(d[1]), "+f"(d[2]), "+f"(d[3])
        : "r"(a[0]), "r"(a[1]), "r"(a[2]), "r"(a[3]), "r"(b[0]), "r"(b[1]));
}

__device__ __forceinline__ void split_f4(float4 v, uint2& hi, uint2& lo) {
    __nv_bfloat162 h0, h1, l0, l1;
    h0.x = __float2bfloat16_rn(v.x); h0.y = __float2bfloat16_rn(v.y);
    h1.x = __float2bfloat16_rn(v.z); h1.y = __float2bfloat16_rn(v.w);
    l0.x = __float2bfloat16_rn(v.x - __bfloat162float(h0.x));
    l0.y = __float2bfloat16_rn(v.y - __bfloat162float(h0.y));
    l1.x = __float2bfloat16_rn(v.z - __bfloat162float(h1.x));
    l1.y = __float2bfloat16_rn(v.w - __bfloat162float(h1.y));
    hi.x = *(uint32_t*)&h0; hi.y = *(uint32_t*)&h1;
    lo.x = *(uint32_t*)&l0; lo.y = *(uint32_t*)&l1;
}

__device__ __forceinline__ void split2(float x, float y, uint32_t& h, uint32_t& l) {
    __nv_bfloat162 hh, ll;
    hh.x = __float2bfloat16_rn(x); hh.y = __float2bfloat16_rn(y);
    ll.x = __float2bfloat16_rn(x - __bfloat162float(hh.x));
    ll.y = __float2bfloat16_rn(y - __bfloat162float(hh.y));
    h = *(uint32_t*)&hh; l = *(uint32_t*)&ll;
}

// ---------------- fp32 -> bf16 hi/lo elementwise split ----------------
__global__ void __launch_bounds__(256) split_kernel(
    const float* __restrict__ src, __nv_bfloat16* __restrict__ hi,
    __nv_bfloat16* __restrict__ lo)
{
    size_t i = (size_t)blockIdx.x * 256 + threadIdx.x;
    float4 v = ((const float4*)src)[i];
    uint2 h, l;
    split_f4(v, h, l);
    *(uint2*)(hi + i * 4) = h;
    *(uint2*)(lo + i * 4) = l;
}

// ---------------- LayerNorm -> bf16 hi/lo planes (plain and/or +pos) ----------------
__global__ void __launch_bounds__(256) ln_split(
    const float* __restrict__ x, const float* __restrict__ w,
    const float* __restrict__ bias, const float* __restrict__ pos,
    __nv_bfloat16* __restrict__ h0, __nv_bfloat16* __restrict__ l0,
    __nv_bfloat16* __restrict__ hp, __nv_bfloat16* __restrict__ lp)
{
    int row = blockIdx.x;
    int tid = threadIdx.x;
    const float4* xr = (const float4*)(x + (size_t)row * E);
    float4 v[4];
    float s = 0.f, sq = 0.f;
#pragma unroll
    for (int i = 0; i < 4; i++) {
        v[i] = xr[tid + 256 * i];
        s  += v[i].x + v[i].y + v[i].z + v[i].w;
        sq += v[i].x * v[i].x + v[i].y * v[i].y + v[i].z * v[i].z + v[i].w * v[i].w;
    }
    __shared__ float s1[256], s2[256];
    s1[tid] = s; s2[tid] = sq;
    __syncthreads();
    for (int st = 128; st > 0; st >>= 1) {
        if (tid < st) { s1[tid] += s1[tid + st]; s2[tid] += s2[tid + st]; }
        __syncthreads();
    }
    float mean = s1[0] * (1.f / E);
    float var  = s2[0] * (1.f / E) - mean * mean;
    float rstd = rsqrtf(var + 1e-5f);

    const float4* wr = (const float4*)w;
    const float4* br = (const float4*)bias;
    const float4* pr = (const float4*)(pos + (size_t)(row & (Nn - 1)) * E);
#pragma unroll
    for (int i = 0; i < 4; i++) {
        int c = tid + 256 * i;
        float4 ww = wr[c], bb = br[c];
        float4 o;
        o.x = (v[i].x - mean) * rstd * ww.x + bb.x;
        o.y = (v[i].y - mean) * rstd * ww.y + bb.y;
        o.z = (v[i].z - mean) * rstd * ww.z + bb.z;
        o.w = (v[i].w - mean) * rstd * ww.w + bb.w;
        size_t off = (size_t)row * E + c * 4;
        uint2 h, l;
        if (h0) {
            split_f4(o, h, l);
            *(uint2*)(h0 + off) = h;
            *(uint2*)(l0 + off) = l;
        }
        if (hp) {
            float4 p = pr[c];
            o.x += p.x; o.y += p.y; o.z += p.z; o.w += p.w;
            split_f4(o, h, l);
            *(uint2*)(hp + off) = h;
            *(uint2*)(lp + off) = l;
        }
    }
}

// ======================= universal pipelined HMMA GEMM, 256x128 tile =======================
// C(256x128 tile) = scale*((Ah+Al)@(Bh+Bl)^T) [+ bias], 3-pass split, fp32 accum.
// 8 warps in 4(m) x 2(n); warp tile 64x64. 2-stage cp.async pipeline, BK=64.
// Batched via blockIdx.z (z = b*32 + h).
#define BK 64
#define APLANE_B 32768
#define BPLANE_B 16384
#define STAGE_B (2 * APLANE_B + 2 * BPLANE_B)   // 96 KB
#define GEMM_SMEM (2 * STAGE_B)                 // 192 KB

__device__ __forceinline__ uint32_t swo(int row, int col) {
    return (uint32_t)(row * 128 + (((col >> 3) ^ (row & 7)) << 4) + (col & 7) * 2);
}

__global__ void __launch_bounds__(256, 1) gemm_u(
    const __nv_bfloat16* __restrict__ Ahp, const __nv_bfloat16* __restrict__ Alp,
    const __nv_bfloat16* __restrict__ Bhp, const __nv_bfloat16* __restrict__ Blp,
    const float* __restrict__ bias, float scale,
    float* __restrict__ Cf,
    __nv_bfloat16* __restrict__ Ch, __nv_bfloat16* __restrict__ Cl,
    size_t aSH, size_t aSB, size_t bSH, size_t bSB, size_t cSH, size_t cSB,
    int lda, int ldb, int ldc, int NIT)
{
    extern __shared__ char sm[];
    const uint32_t sbase = smem_u32(sm);
    const int tid  = threadIdx.x;
    const int wid  = tid >> 5;
    const int lane = tid & 31;
    const int g    = lane >> 2;
    const int tq   = lane & 3;
    const int wm   = (wid >> 1) * 64;     // 4 warps along M
    const int wn   = (wid & 1) * 64;      // 2 warps along N
    const int m0 = blockIdx.y * 256;
    const int n0 = blockIdx.x * 128;
    const int z  = blockIdx.z;
    const int hz = z & 31, bz = z >> 5;
    const size_t aOff = (size_t)hz * aSH + (size_t)bz * aSB;
    const size_t bOff = (size_t)hz * bSH + (size_t)bz * bSB;
    const size_t cOff = (size_t)hz * cSH + (size_t)bz * cSB;

    const __nv_bfloat16* p0 = Ahp + aOff + (size_t)m0 * lda;
    const __nv_bfloat16* p1 = Alp + aOff + (size_t)m0 * lda;
    const __nv_bfloat16* p2 = Bhp + bOff + (size_t)n0 * ldb;
    const __nv_bfloat16* p3 = Blp + bOff + (size_t)n0 * ldb;

    float acc[4][8][4];
#pragma unroll
    for (int i = 0; i < 4; i++)
#pragma unroll
        for (int j = 0; j < 8; j++)
#pragma unroll
            for (int k = 0; k < 4; k++) acc[i][j][k] = 0.f;

    auto issue = [&](int slot, int kt) {
        uint32_t sb = sbase + slot * STAGE_B;
        // A planes: 256 rows x 64 cols each
#pragma unroll
        for (int j = 0; j < 8; j++) {
            int idx = tid + 256 * j;
            int row = idx >> 3;
            int c   = idx & 7;
            uint32_t so = row * 128 + ((c ^ (row & 7)) << 4);
            cp_async16(sb + so, p0 + (size_t)row * lda + kt + c * 8);
            cp_async16(sb + APLANE_B + so, p1 + (size_t)row * lda + kt + c * 8);
        }
        // B planes: 128 rows x 64 cols each
#pragma unroll
        for (int j = 0; j < 4; j++) {
            int idx = tid + 256 * j;
            int row = idx >> 3;
            int c   = idx & 7;
            uint32_t so = row * 128 + ((c ^ (row & 7)) << 4);
            cp_async16(sb + 2 * APLANE_B + so, p2 + (size_t)row * ldb + kt + c * 8);
            cp_async16(sb + 2 * APLANE_B + BPLANE_B + so, p3 + (size_t)row * ldb + kt + c * 8);
        }
    };

    issue(0, 0);  CP_COMMIT();
    if (NIT > 1) issue(1, BK);
    CP_COMMIT();

    for (int it = 0; it < NIT; it++) {
        CP_WAIT1();
        __syncthreads();

        const char* base = sm + (it & 1) * STAGE_B;
        const char* Ahs = base;
        const char* Als = base + APLANE_B;
        const char* Bhs = base + 2 * APLANE_B;
        const char* Bls = base + 2 * APLANE_B + BPLANE_B;
#pragma unroll
        for (int ks = 0; ks < BK; ks += 16) {
            uint32_t ah[4][4], al[4][4], bf[8][2];
#pragma unroll
            for (int mt = 0; mt < 4; mt++)
#pragma unroll
                for (int r = 0; r < 4; r++) {
                    int row = wm + mt * 16 + g + (r & 1) * 8;
                    int col = ks + tq * 2 + (r >> 1) * 8;
                    ah[mt][r] = *(const uint32_t*)(Ahs + swo(row, col));
                    al[mt][r] = *(const uint32_t*)(Als + swo(row, col));
                }
#pragma unroll
            for (int nt = 0; nt < 8; nt++) {
                int row = wn + nt * 8 + g;
                bf[nt][0] = *(const uint32_t*)(Bhs + swo(row, ks + tq * 2));
                bf[nt][1] = *(const uint32_t*)(Bhs + swo(row, ks + tq * 2 + 8));
            }
#pragma unroll
            for (int mt = 0; mt < 4; mt++)
#pragma unroll
                for (int nt = 0; nt < 8; nt++) mma16816(acc[mt][nt], ah[mt], bf[nt]);
#pragma unroll
            for (int mt = 0; mt < 4; mt++)
#pragma unroll
                for (int nt = 0; nt < 8; nt++) mma16816(acc[mt][nt], al[mt], bf[nt]);
#pragma unroll
            for (int nt = 0; nt < 8; nt++) {
                int row = wn + nt * 8 + g;
                bf[nt][0] = *(const uint32_t*)(Bls + swo(row, ks + tq * 2));
                bf[nt][1] = *(const uint32_t*)(Bls + swo(row, ks + tq * 2 + 8));
            }
#pragma unroll
            for (int mt = 0; mt < 4; mt++)
#pragma unroll
                for (int nt = 0; nt < 8; nt++) mma16816(acc[mt][nt], ah[mt], bf[nt]);
        }
        __syncthreads();
        if (it + 2 < NIT) issue((it + 2) & 1, (it + 2) * BK);
        CP_COMMIT();
    }

    // epilogue
    float bn[8][2];
#pragma unroll
    for (int nt = 0; nt < 8; nt++) {
        if (bias) {
            int n = n0 + wn + nt * 8 + tq * 2;
            bn[nt][0] = bias[n];
            bn[nt][1] = bias[n + 1];
        } else {
            bn[nt][0] = 0.f; bn[nt][1] = 0.f;
        }
    }
#pragma unroll
    for (int mt = 0; mt < 4; mt++)
#pragma unroll
        for (int half = 0; half < 2; half++) {
            int m = m0 + wm + mt * 16 + g + half * 8;
#pragma unroll
            for (int nt = 0; nt < 8; nt++) {
                float vx = acc[mt][nt][half * 2 + 0] * scale + bn[nt][0];
                float vy = acc[mt][nt][half * 2 + 1] * scale + bn[nt][1];
                size_t off = cOff + (size_t)m * ldc + n0 + wn + nt * 8 + tq * 2;
                if (Cf) *(float2*)(Cf + off) = make_float2(vx, vy);
                if (Ch) {
                    uint32_t h, l;
                    split2(vx, vy, h, l);
                    *(uint32_t*)(Ch + off) = h;
                    *(uint32_t*)(Cl + off) = l;
                }
            }
        }
}

// ---------------- V planes -> V^T planes per (b,h): [n][d] -> [d][n] ----------------
__global__ void __launch_bounds__(256) vtrans(
    const __nv_bfloat16* __restrict__ Vh, const __nv_bfloat16* __restrict__ Vl,
    __nv_bfloat16* __restrict__ Vth, __nv_bfloat16* __restrict__ Vtl)
{
    __shared__ __nv_bfloat16 t0[32][33], t1[32][33];
    int z = blockIdx.z;
    int hz = z & 31, bz = z >> 5;
    int d0 = blockIdx.x * 32;
    int n0 = blockIdx.y * 32;
    int tx = threadIdx.x & 31, ty = threadIdx.x >> 5;   // 32 x 8
#pragma unroll
    for (int i = 0; i < 4; i++) {
        int n = n0 + ty + i * 8;
        size_t src = ((size_t)bz * Nn + n) * E + hz * Dd + d0 + tx;
        t0[ty + i * 8][tx] = Vh[src];
        t1[ty + i * 8][tx] = Vl[src];
    }
    __syncthreads();
#pragma unroll
    for (int i = 0; i < 4; i++) {
        int d = d0 + ty + i * 8;
        size_t dst = ((size_t)z * Dd + d) * Nn + n0 + tx;
        Vth[dst] = t0[tx][ty + i * 8];
        Vtl[dst] = t1[tx][ty + i * 8];
    }
}

// ---------------- softmax over n; writes fp32 in-place + bf16 hi/lo planes ----------------
__global__ void __launch_bounds__(256) softmax_kernel(
    float* __restrict__ attn,
    __nv_bfloat16* __restrict__ Ph, __nv_bfloat16* __restrict__ Pl)
{
    int warp = threadIdx.x >> 5, lane = threadIdx.x & 31;
    size_t row = (size_t)blockIdx.x * 8 + warp;
    float4* p = (float4*)(attn + row * Nn);
    float4 v0 = p[lane];
    float4 v1 = p[lane + 32];
    float mx = fmaxf(fmaxf(fmaxf(v0.x, v0.y), fmaxf(v0.z, v0.w)),
                     fmaxf(fmaxf(v1.x, v1.y), fmaxf(v1.z, v1.w)));
#pragma unroll
    for (int o = 16; o; o >>= 1) mx = fmaxf(mx, __shfl_xor_sync(0xffffffffu, mx, o));
    v0.x = expf(v0.x - mx); v0.y = expf(v0.y - mx);
    v0.z = expf(v0.z - mx); v0.w = expf(v0.w - mx);
    v1.x = expf(v1.x - mx); v1.y = expf(v1.y - mx);
    v1.z = expf(v1.z - mx); v1.w = expf(v1.w - mx);
    float s = v0.x + v0.y + v0.z + v0.w + v1.x + v1.y + v1.z + v1.w;
#pragma unroll
    for (int o = 16; o; o >>= 1) s += __shfl_xor_sync(0xffffffffu, s, o);
    float inv = 1.f / s;
    v0.x *= inv; v0.y *= inv; v0.z *= inv; v0.w *= inv;
    v1.x *= inv; v1.y *= inv; v1.z *= inv; v1.w *= inv;
    p[lane] = v0;
    p[lane + 32] = v1;
    uint2 h, l;
    split_f4(v0, h, l);
    *(uint2*)(Ph + row * Nn + lane * 4) = h;
    *(uint2*)(Pl + row * Nn + lane * 4) = l;
    split_f4(v1, h, l);
    *(uint2*)(Ph + row * Nn + 128 + lane * 4) = h;
    *(uint2*)(Pl + row * Nn + 128 + lane * 4) = l;
}

// ---------------- attn mean over heads ----------------
__global__ void __launch_bounds__(256) attn_mean_kernel(
    const float* __restrict__ attn, float* __restrict__ out)
{
    int idx = blockIdx.x * 256 + threadIdx.x;
    int b = idx / (Mm * Nn);
    int rem = idx - b * (Mm * Nn);
    const float* p = attn + (size_t)b * Hh * Mm * Nn + rem;
    float s = 0.f;
#pragma unroll
    for (int h = 0; h < Hh; h++) s += p[(size_t)h * Mm * Nn];
    out[idx] = s * (1.f / Hh);
}

// ---------------- launcher ----------------
extern "C" void kernel_launch(void* const* d_in, const int* in_sizes, int n_in,
                              void* d_out, int out_size)
{
    const float* x       = (const float*)d_in[0];
    const float* query   = (const float*)d_in[1];
    const float* pos     = (const float*)d_in[2];
    const float* ln_q_w  = (const float*)d_in[3];
    const float* ln_q_b  = (const float*)d_in[4];
    const float* ln_kv_w = (const float*)d_in[5];
    const float* ln_kv_b = (const float*)d_in[6];
    const float* in_w    = (const float*)d_in[7];
    const float* in_b    = (const float*)d_in[8];
    const float* out_w   = (const float*)d_in[9];
    const float* out_b   = (const float*)d_in[10];
    float* out = (float*)d_out;

    float *attn;
    cudaGetSymbolAddress((void**)&attn, g_attn);
    __nv_bfloat16 *qh, *ql, *kvh, *kvl, *kvph, *kvpl;
    __nv_bfloat16 *Qh, *Ql, *Kh, *Kl, *Vh, *Vl, *Vth, *Vtl, *Ph, *Pl, *oh, *ol, *wh, *wl;
    cudaGetSymbolAddress((void**)&qh,   g_qh);
    cudaGetSymbolAddress((void**)&ql,   g_ql);
    cudaGetSymbolAddress((void**)&kvh,  g_kvh);
    cudaGetSymbolAddress((void**)&kvl,  g_kvl);
    cudaGetSymbolAddress((void**)&kvph, g_kvph);
    cudaGetSymbolAddress((void**)&kvpl, g_kvpl);
    cudaGetSymbolAddress((void**)&Qh,   g_Qh);
    cudaGetSymbolAddress((void**)&Ql,   g_Ql);
    cudaGetSymbolAddress((void**)&Kh,   g_Kh);
    cudaGetSymbolAddress((void**)&Kl,   g_Kl);
    cudaGetSymbolAddress((void**)&Vh,   g_Vh);
    cudaGetSymbolAddress((void**)&Vl,   g_Vl);
    cudaGetSymbolAddress((void**)&Vth,  g_Vth);
    cudaGetSymbolAddress((void**)&Vtl,  g_Vtl);
    cudaGetSymbolAddress((void**)&Ph,   g_Ph);
    cudaGetSymbolAddress((void**)&Pl,   g_Pl);
    cudaGetSymbolAddress((void**)&oh,   g_oh);
    cudaGetSymbolAddress((void**)&ol,   g_ol);
    cudaGetSymbolAddress((void**)&wh,   g_wh);
    cudaGetSymbolAddress((void**)&wl,   g_wl);

    cudaFuncSetAttribute(gemm_u, cudaFuncAttributeMaxDynamicSharedMemorySize, GEMM_SMEM);

    // 0) split weights
    split_kernel<<<(3ULL * E * E / 4) / 256, 256>>>(in_w, wh, wl);
    split_kernel<<<((size_t)E * E / 4) / 256, 256>>>(out_w, wh + 3ULL * E * E, wl + 3ULL * E * E);

    // 1) LayerNorms -> split planes
    ln_split<<<Bb * Nn, 256>>>(x, ln_kv_w, ln_kv_b, pos, kvh, kvl, kvph, kvpl);
    ln_split<<<Mm, 256>>>(query, ln_q_w, ln_q_b, pos, nullptr, nullptr, qh, ql);

    // 2) Projections -> split planes directly (256x128 tiles)
    gemm_u<<<dim3(32, 1, 1), 256, GEMM_SMEM>>>(
        qh, ql, wh, wl, in_b, 1.f, nullptr, Qh, Ql,
        0, 0, 0, 0, 0, 0, E, E, E, E / BK);
    gemm_u<<<dim3(32, 8, 1), 256, GEMM_SMEM>>>(
        kvph, kvpl, wh + (size_t)E * E, wl + (size_t)E * E, in_b + E, 1.f, nullptr, Kh, Kl,
        0, 0, 0, 0, 0, 0, E, E, E, E / BK);
    gemm_u<<<dim3(32, 8, 1), 256, GEMM_SMEM>>>(
        kvh, kvl, wh + 2ULL * E * E, wl + 2ULL * E * E, in_b + 2 * E, 1.f, nullptr, Vh, Vl,
        0, 0, 0, 0, 0, 0, E, E, E, E / BK);

    // 3) V transpose -> [bh][d][n]
    vtrans<<<dim3(Dd / 32, Nn / 32, Bb * Hh), 256>>>(Vh, Vl, Vth, Vtl);

    // 4) scores = Q @ K^T / sqrt(D)   (batched over bh)
    gemm_u<<<dim3(2, 1, Bb * Hh), 256, GEMM_SMEM>>>(
        Qh, Ql, Kh, Kl, nullptr, 0.08838834764831845f, attn, nullptr, nullptr,
        (size_t)Dd, 0, (size_t)Dd, (size_t)Nn * E,
        (size_t)Mm * Nn, 32ULL * Mm * Nn, E, E, Nn, Dd / BK);

    // 5) softmax (+ P planes)
    softmax_kernel<<<Bb * Hh * Mm / 8, 256>>>(attn, Ph, Pl);

    // 6) O = P @ V   (batched over bh) -> O split planes
    gemm_u<<<dim3(1, 1, Bb * Hh), 256, GEMM_SMEM>>>(
        Ph, Pl, Vth, Vtl, nullptr, 1.f, nullptr, oh, ol,
        (size_t)Mm * Nn, 32ULL * Mm * Nn, (size_t)Dd * Nn, 32ULL * Dd * Nn,
        (size_t)Dd, (size_t)Mm * E, Nn, Nn, E, Nn / BK);

    // 7) out projection -> d_out
    gemm_u<<<dim3(32, 8, 1), 256, GEMM_SMEM>>>(
        oh, ol, wh + 3ULL * E * E, wl + 3ULL * E * E, out_b, 1.f, out, nullptr, nullptr,
        0, 0, 0, 0, 0, 0, E, E, E, E / BK);

    // 8) attn.mean(heads)
    attn_mean_kernel<<<Bb * Mm * Nn / 256, 256>>>(attn, out + (size_t)Bb * Mm * E);
}

// round 7
// speedup vs baseline: 4.0662x; 1.3750x over previous
#include <cuda_runtime.h>
#include <cuda_fp16.h>
#include <cstdint>
#include <math.h>

#define E  4096
#define Hh 32
#define Mm 256
#define Bb 8
#define Nn 256
#define Dd 128

// ---------------- scratch (alloc-free: __device__ globals) ----------------
__device__ float g_attn[Bb * Hh * Mm * Nn];

// fp16 hi/lo planes
__device__ __half g_qh[Mm * E],        g_ql[Mm * E];           // LN(query)+pos
__device__ __half g_kvh[Bb * Nn * E],  g_kvl[Bb * Nn * E];     // LN(x)
__device__ __half g_kvph[Bb * Nn * E], g_kvpl[Bb * Nn * E];    // LN(x)+pos
__device__ __half g_Qh[Mm * E],        g_Ql[Mm * E];           // Q proj
__device__ __half g_Kh[Bb * Nn * E],   g_Kl[Bb * Nn * E];      // K proj
__device__ __half g_Vh[Bb * Nn * E],   g_Vl[Bb * Nn * E];      // V proj
__device__ __half g_Vth[Bb * Hh * Dd * Nn], g_Vtl[Bb * Hh * Dd * Nn]; // V^T per (b,h)
__device__ __half g_Ph[Bb * Hh * Mm * Nn],  g_Pl[Bb * Hh * Mm * Nn];  // softmax planes
__device__ __half g_oh[Bb * Mm * E],   g_ol[Bb * Mm * E];      // attn output
__device__ __half g_wh[4ULL * E * E];                          // Wq,Wk,Wv,Wo hi
__device__ __half g_wl[2ULL * E * E];                          // Wq,Wk lo (only ones needed)

// ---------------- helpers ----------------
__device__ __forceinline__ uint32_t smem_u32(const void* p) {
    uint32_t a;
    asm("{ .reg .u64 t; cvta.to.shared.u64 t, %1; cvt.u32.u64 %0, t; }"
        : "=r"(a) : "l"(p));
    return a;
}

__device__ __forceinline__ void cp_async16(uint32_t dst, const void* src) {
    asm volatile("cp.async.cg.shared.global [%0], [%1], 16;"
                 :: "r"(dst), "l"(src) : "memory");
}
#define CP_COMMIT() asm volatile("cp.async.commit_group;" ::: "memory")
#define CP_WAIT1()  asm volatile("cp.async.wait_group 1;" ::: "memory")

__device__ __forceinline__ void mma16816(float* d, const uint32_t* a, const uint32_t* b) {
    asm volatile(
        "mma.sync.aligned.m16n8k16.row.col.f32.f16.f16.f32 "
        "{%0,%1,%2,%3}, {%4,%5,%6,%7}, {%8,%9}, {%0,%1,%2,%3};"
        : "+f"(d[0]), "+f"(d[1]), "+f"(d[2]), "+f"(d[3])
        : "r"(a[0]), "r"(a[1]), "r"(a[2]), "r"(a[3]), "r"(b[0]), "r"(b[1]));
}

__device__ __forceinline__ void split_f4(float4 v, uint2& hi, uint2& lo) {
    __half2 h0 = __floats2half2_rn(v.x, v.y);
    __half2 h1 = __floats2half2_rn(v.z, v.w);
    float2 f0 = __half22float2(h0), f1 = __half22float2(h1);
    __half2 l0 = __floats2half2_rn(v.x - f0.x, v.y - f0.y);
    __half2 l1 = __floats2half2_rn(v.z - f1.x, v.w - f1.y);
    hi.x = *(uint32_t*)&h0; hi.y = *(uint32_t*)&h1;
    lo.x = *(uint32_t*)&l0; lo.y = *(uint32_t*)&l1;
}

__device__ __forceinline__ void split2(float x, float y, uint32_t& h, uint32_t& l) {
    __half2 hh = __floats2half2_rn(x, y);
    float2 f = __half22float2(hh);
    __half2 ll = __floats2half2_rn(x - f.x, y - f.y);
    h = *(uint32_t*)&hh; l = *(uint32_t*)&ll;
}

// ---------------- fp32 -> fp16 hi/lo elementwise split (lo optional) ----------------
__global__ void __launch_bounds__(256) split_kernel(
    const float* __restrict__ src, __half* __restrict__ hi,
    __half* __restrict__ lo)
{
    size_t i = (size_t)blockIdx.x * 256 + threadIdx.x;
    float4 v = ((const float4*)src)[i];
    uint2 h, l;
    split_f4(v, h, l);
    *(uint2*)(hi + i * 4) = h;
    if (lo) *(uint2*)(lo + i * 4) = l;
}

// ---------------- LayerNorm -> fp16 hi/lo planes (plain and/or +pos) ----------------
__global__ void __launch_bounds__(256) ln_split(
    const float* __restrict__ x, const float* __restrict__ w,
    const float* __restrict__ bias, const float* __restrict__ pos,
    __half* __restrict__ h0, __half* __restrict__ l0,
    __half* __restrict__ hp, __half* __restrict__ lp)
{
    int row = blockIdx.x;
    int tid = threadIdx.x;
    const float4* xr = (const float4*)(x + (size_t)row * E);
    float4 v[4];
    float s = 0.f, sq = 0.f;
#pragma unroll
    for (int i = 0; i < 4; i++) {
        v[i] = xr[tid + 256 * i];
        s  += v[i].x + v[i].y + v[i].z + v[i].w;
        sq += v[i].x * v[i].x + v[i].y * v[i].y + v[i].z * v[i].z + v[i].w * v[i].w;
    }
    __shared__ float s1[256], s2[256];
    s1[tid] = s; s2[tid] = sq;
    __syncthreads();
    for (int st = 128; st > 0; st >>= 1) {
        if (tid < st) { s1[tid] += s1[tid + st]; s2[tid] += s2[tid + st]; }
        __syncthreads();
    }
    float mean = s1[0] * (1.f / E);
    float var  = s2[0] * (1.f / E) - mean * mean;
    float rstd = rsqrtf(var + 1e-5f);

    const float4* wr = (const float4*)w;
    const float4* br = (const float4*)bias;
    const float4* pr = (const float4*)(pos + (size_t)(row & (Nn - 1)) * E);
#pragma unroll
    for (int i = 0; i < 4; i++) {
        int c = tid + 256 * i;
        float4 ww = wr[c], bb = br[c];
        float4 o;
        o.x = (v[i].x - mean) * rstd * ww.x + bb.x;
        o.y = (v[i].y - mean) * rstd * ww.y + bb.y;
        o.z = (v[i].z - mean) * rstd * ww.z + bb.z;
        o.w = (v[i].w - mean) * rstd * ww.w + bb.w;
        size_t off = (size_t)row * E + c * 4;
        uint2 h, l;
        if (h0) {
            split_f4(o, h, l);
            *(uint2*)(h0 + off) = h;
            *(uint2*)(l0 + off) = l;
        }
        if (hp) {
            float4 p = pr[c];
            o.x += p.x; o.y += p.y; o.z += p.z; o.w += p.w;
            split_f4(o, h, l);
            *(uint2*)(hp + off) = h;
            *(uint2*)(lp + off) = l;
        }
    }
}

// ======================= universal pipelined HMMA GEMM, 256x128 tile =======================
// NPASS=3: C = Ah.Bh + Al.Bh + Ah.Bl (split both);  NPASS=2: C = Ah.Bh + Al.Bh (B hi only).
// QM: last grid.y tile uses the z* operand set (merged second GEMM with M=256).
#define BK 64
#define APLANE_B 32768
#define BPLANE_B 16384
#define STAGE_B (2 * APLANE_B + 2 * BPLANE_B)   // 96 KB
#define GEMM_SMEM (2 * STAGE_B)                 // 192 KB

__device__ __forceinline__ uint32_t swo(int row, int col) {
    return (uint32_t)(row * 128 + (((col >> 3) ^ (row & 7)) << 4) + (col & 7) * 2);
}

template <int NPASS, bool QM>
__global__ void __launch_bounds__(256, 1) gemm_u(
    const __half* __restrict__ Ahp, const __half* __restrict__ Alp,
    const __half* __restrict__ Bhp, const __half* __restrict__ Blp,
    const float* __restrict__ bias, float scale,
    float* __restrict__ Cf,
    __half* __restrict__ Ch, __half* __restrict__ Cl,
    size_t aSH, size_t aSB, size_t bSH, size_t bSB, size_t cSH, size_t cSB,
    int lda, int ldb, int ldc, int NIT,
    const __half* zAh, const __half* zAl, const __half* zBh, const __half* zBl,
    const float* zbias, __half* zCh, __half* zCl)
{
    extern __shared__ char sm[];
    const uint32_t sbase = smem_u32(sm);
    const int tid  = threadIdx.x;
    const int wid  = tid >> 5;
    const int lane = tid & 31;
    const int g    = lane >> 2;
    const int tq   = lane & 3;
    const int wm   = (wid >> 1) * 64;
    const int wn   = (wid & 1) * 64;
    const bool qb = QM && (blockIdx.y == gridDim.y - 1);
    const int m0 = qb ? 0 : blockIdx.y * 256;
    const int n0 = blockIdx.x * 128;
    const int z  = blockIdx.z;
    const int hz = z & 31, bz = z >> 5;
    const size_t aOff = (size_t)hz * aSH + (size_t)bz * aSB;
    const size_t bOff = (size_t)hz * bSH + (size_t)bz * bSB;
    const size_t cOff = (size_t)hz * cSH + (size_t)bz * cSB;

    const __half* p0 = (qb ? zAh : Ahp + aOff) + (size_t)m0 * lda;
    const __half* p1 = (qb ? zAl : Alp + aOff) + (size_t)m0 * lda;
    const __half* p2 = (qb ? zBh : Bhp + bOff) + (size_t)n0 * ldb;
    const __half* p3 = (NPASS == 3) ? ((qb ? zBl : Blp + bOff) + (size_t)n0 * ldb) : nullptr;
    const float* bptr = qb ? zbias : bias;
    __half* och = qb ? zCh : Ch;
    __half* ocl = qb ? zCl : Cl;
    float* ocf = qb ? nullptr : Cf;

    float acc[4][8][4];
#pragma unroll
    for (int i = 0; i < 4; i++)
#pragma unroll
        for (int j = 0; j < 8; j++)
#pragma unroll
            for (int k = 0; k < 4; k++) acc[i][j][k] = 0.f;

    auto issue = [&](int slot, int kt) {
        uint32_t sb = sbase + slot * STAGE_B;
#pragma unroll
        for (int j = 0; j < 8; j++) {
            int idx = tid + 256 * j;
            int row = idx >> 3;
            int c   = idx & 7;
            uint32_t so = row * 128 + ((c ^ (row & 7)) << 4);
            cp_async16(sb + so, p0 + (size_t)row * lda + kt + c * 8);
            cp_async16(sb + APLANE_B + so, p1 + (size_t)row * lda + kt + c * 8);
        }
#pragma unroll
        for (int j = 0; j < 4; j++) {
            int idx = tid + 256 * j;
            int row = idx >> 3;
            int c   = idx & 7;
            uint32_t so = row * 128 + ((c ^ (row & 7)) << 4);
            cp_async16(sb + 2 * APLANE_B + so, p2 + (size_t)row * ldb + kt + c * 8);
            if (NPASS == 3)
                cp_async16(sb + 2 * APLANE_B + BPLANE_B + so, p3 + (size_t)row * ldb + kt + c * 8);
        }
    };

    issue(0, 0);  CP_COMMIT();
    if (NIT > 1) issue(1, BK);
    CP_COMMIT();

    for (int it = 0; it < NIT; it++) {
        CP_WAIT1();
        __syncthreads();

        const char* base = sm + (it & 1) * STAGE_B;
        const char* Ahs = base;
        const char* Als = base + APLANE_B;
        const char* Bhs = base + 2 * APLANE_B;
        const char* Bls = base + 2 * APLANE_B + BPLANE_B;
#pragma unroll
        for (int ks = 0; ks < BK; ks += 16) {
            uint32_t ah[4][4], al[4][4], bf[8][2];
#pragma unroll
            for (int mt = 0; mt < 4; mt++)
#pragma unroll
                for (int r = 0; r < 4; r++) {
                    int row = wm + mt * 16 + g + (r & 1) * 8;
                    int col = ks + tq * 2 + (r >> 1) * 8;
                    ah[mt][r] = *(const uint32_t*)(Ahs + swo(row, col));
                    al[mt][r] = *(const uint32_t*)(Als + swo(row, col));
                }
#pragma unroll
            for (int nt = 0; nt < 8; nt++) {
                int row = wn + nt * 8 + g;
                bf[nt][0] = *(const uint32_t*)(Bhs + swo(row, ks + tq * 2));
                bf[nt][1] = *(const uint32_t*)(Bhs + swo(row, ks + tq * 2 + 8));
            }
#pragma unroll
            for (int mt = 0; mt < 4; mt++)
#pragma unroll
                for (int nt = 0; nt < 8; nt++) mma16816(acc[mt][nt], ah[mt], bf[nt]);
#pragma unroll
            for (int mt = 0; mt < 4; mt++)
#pragma unroll
                for (int nt = 0; nt < 8; nt++) mma16816(acc[mt][nt], al[mt], bf[nt]);
            if (NPASS == 3) {
#pragma unroll
                for (int nt = 0; nt < 8; nt++) {
                    int row = wn + nt * 8 + g;
                    bf[nt][0] = *(const uint32_t*)(Bls + swo(row, ks + tq * 2));
                    bf[nt][1] = *(const uint32_t*)(Bls + swo(row, ks + tq * 2 + 8));
                }
#pragma unroll
                for (int mt = 0; mt < 4; mt++)
#pragma unroll
                    for (int nt = 0; nt < 8; nt++) mma16816(acc[mt][nt], ah[mt], bf[nt]);
            }
        }
        __syncthreads();
        if (it + 2 < NIT) issue((it + 2) & 1, (it + 2) * BK);
        CP_COMMIT();
    }

    // epilogue
    float bn[8][2];
#pragma unroll
    for (int nt = 0; nt < 8; nt++) {
        if (bptr) {
            int n = n0 + wn + nt * 8 + tq * 2;
            bn[nt][0] = bptr[n];
            bn[nt][1] = bptr[n + 1];
        } else {
            bn[nt][0] = 0.f; bn[nt][1] = 0.f;
        }
    }
#pragma unroll
    for (int mt = 0; mt < 4; mt++)
#pragma unroll
        for (int half = 0; half < 2; half++) {
            int m = m0 + wm + mt * 16 + g + half * 8;
#pragma unroll
            for (int nt = 0; nt < 8; nt++) {
                float vx = acc[mt][nt][half * 2 + 0] * scale + bn[nt][0];
                float vy = acc[mt][nt][half * 2 + 1] * scale + bn[nt][1];
                size_t off = cOff + (size_t)m * ldc + n0 + wn + nt * 8 + tq * 2;
                if (ocf) *(float2*)(ocf + off) = make_float2(vx, vy);
                if (och) {
                    uint32_t h, l;
                    split2(vx, vy, h, l);
                    *(uint32_t*)(och + off) = h;
                    *(uint32_t*)(ocl + off) = l;
                }
            }
        }
}

// ---------------- V planes -> V^T planes per (b,h): [n][d] -> [d][n] ----------------
__global__ void __launch_bounds__(256) vtrans(
    const __half* __restrict__ Vh, const __half* __restrict__ Vl,
    __half* __restrict__ Vth, __half* __restrict__ Vtl)
{
    __shared__ __half t0[32][33], t1[32][33];
    int z = blockIdx.z;
    int hz = z & 31, bz = z >> 5;
    int d0 = blockIdx.x * 32;
    int n0 = blockIdx.y * 32;
    int tx = threadIdx.x & 31, ty = threadIdx.x >> 5;
#pragma unroll
    for (int i = 0; i < 4; i++) {
        int n = n0 + ty + i * 8;
        size_t src = ((size_t)bz * Nn + n) * E + hz * Dd + d0 + tx;
        t0[ty + i * 8][tx] = Vh[src];
        t1[ty + i * 8][tx] = Vl[src];
    }
    __syncthreads();
#pragma unroll
    for (int i = 0; i < 4; i++) {
        int d = d0 + ty + i * 8;
        size_t dst = ((size_t)z * Dd + d) * Nn + n0 + tx;
        Vth[dst] = t0[tx][ty + i * 8];
        Vtl[dst] = t1[tx][ty + i * 8];
    }
}

// ---------------- softmax over n; writes fp32 in-place + fp16 hi/lo planes ----------------
__global__ void __launch_bounds__(256) softmax_kernel(
    float* __restrict__ attn,
    __half* __restrict__ Ph, __half* __restrict__ Pl)
{
    int warp = threadIdx.x >> 5, lane = threadIdx.x & 31;
    size_t row = (size_t)blockIdx.x * 8 + warp;
    float4* p = (float4*)(attn + row * Nn);
    float4 v0 = p[lane];
    float4 v1 = p[lane + 32];
    float mx = fmaxf(fmaxf(fmaxf(v0.x, v0.y), fmaxf(v0.z, v0.w)),
                     fmaxf(fmaxf(v1.x, v1.y), fmaxf(v1.z, v1.w)));
#pragma unroll
    for (int o = 16; o; o >>= 1) mx = fmaxf(mx, __shfl_xor_sync(0xffffffffu, mx, o));
    v0.x = expf(v0.x - mx); v0.y = expf(v0.y - mx);
    v0.z = expf(v0.z - mx); v0.w = expf(v0.w - mx);
    v1.x = expf(v1.x - mx); v1.y = expf(v1.y - mx);
    v1.z = expf(v1.z - mx); v1.w = expf(v1.w - mx);
    float s = v0.x + v0.y + v0.z + v0.w + v1.x + v1.y + v1.z + v1.w;
#pragma unroll
    for (int o = 16; o; o >>= 1) s += __shfl_xor_sync(0xffffffffu, s, o);
    float inv = 1.f / s;
    v0.x *= inv; v0.y *= inv; v0.z *= inv; v0.w *= inv;
    v1.x *= inv; v1.y *= inv; v1.z *= inv; v1.w *= inv;
    p[lane] = v0;
    p[lane + 32] = v1;
    uint2 h, l;
    split_f4(v0, h, l);
    *(uint2*)(Ph + row * Nn + lane * 4) = h;
    *(uint2*)(Pl + row * Nn + lane * 4) = l;
    split_f4(v1, h, l);
    *(uint2*)(Ph + row * Nn + 128 + lane * 4) = h;
    *(uint2*)(Pl + row * Nn + 128 + lane * 4) = l;
}

// ---------------- attn mean over heads ----------------
__global__ void __launch_bounds__(256) attn_mean_kernel(
    const float* __restrict__ attn, float* __restrict__ out)
{
    int idx = blockIdx.x * 256 + threadIdx.x;
    int b = idx / (Mm * Nn);
    int rem = idx - b * (Mm * Nn);
    const float* p = attn + (size_t)b * Hh * Mm * Nn + rem;
    float s = 0.f;
#pragma unroll
    for (int h = 0; h < Hh; h++) s += p[(size_t)h * Mm * Nn];
    out[idx] = s * (1.f / Hh);
}

// ---------------- launcher ----------------
extern "C" void kernel_launch(void* const* d_in, const int* in_sizes, int n_in,
                              void* d_out, int out_size)
{
    const float* x       = (const float*)d_in[0];
    const float* query   = (const float*)d_in[1];
    const float* pos     = (const float*)d_in[2];
    const float* ln_q_w  = (const float*)d_in[3];
    const float* ln_q_b  = (const float*)d_in[4];
    const float* ln_kv_w = (const float*)d_in[5];
    const float* ln_kv_b = (const float*)d_in[6];
    const float* in_w    = (const float*)d_in[7];
    const float* in_b    = (const float*)d_in[8];
    const float* out_w   = (const float*)d_in[9];
    const float* out_b   = (const float*)d_in[10];
    float* out = (float*)d_out;

    float *attn;
    cudaGetSymbolAddress((void**)&attn, g_attn);
    __half *qh, *ql, *kvh, *kvl, *kvph, *kvpl;
    __half *Qh, *Ql, *Kh, *Kl, *Vh, *Vl, *Vth, *Vtl, *Ph, *Pl, *oh, *ol, *wh, *wl;
    cudaGetSymbolAddress((void**)&qh,   g_qh);
    cudaGetSymbolAddress((void**)&ql,   g_ql);
    cudaGetSymbolAddress((void**)&kvh,  g_kvh);
    cudaGetSymbolAddress((void**)&kvl,  g_kvl);
    cudaGetSymbolAddress((void**)&kvph, g_kvph);
    cudaGetSymbolAddress((void**)&kvpl, g_kvpl);
    cudaGetSymbolAddress((void**)&Qh,   g_Qh);
    cudaGetSymbolAddress((void**)&Ql,   g_Ql);
    cudaGetSymbolAddress((void**)&Kh,   g_Kh);
    cudaGetSymbolAddress((void**)&Kl,   g_Kl);
    cudaGetSymbolAddress((void**)&Vh,   g_Vh);
    cudaGetSymbolAddress((void**)&Vl,   g_Vl);
    cudaGetSymbolAddress((void**)&Vth,  g_Vth);
    cudaGetSymbolAddress((void**)&Vtl,  g_Vtl);
    cudaGetSymbolAddress((void**)&Ph,   g_Ph);
    cudaGetSymbolAddress((void**)&Pl,   g_Pl);
    cudaGetSymbolAddress((void**)&oh,   g_oh);
    cudaGetSymbolAddress((void**)&ol,   g_ol);
    cudaGetSymbolAddress((void**)&wh,   g_wh);
    cudaGetSymbolAddress((void**)&wl,   g_wl);

    cudaFuncSetAttribute(gemm_u<3, true>,  cudaFuncAttributeMaxDynamicSharedMemorySize, GEMM_SMEM);
    cudaFuncSetAttribute(gemm_u<3, false>, cudaFuncAttributeMaxDynamicSharedMemorySize, GEMM_SMEM);
    cudaFuncSetAttribute(gemm_u<2, false>, cudaFuncAttributeMaxDynamicSharedMemorySize, GEMM_SMEM);

    // 0) split weights: Wq,Wk need hi+lo (3-pass); Wv,Wo hi only (2-pass)
    split_kernel<<<(2ULL * E * E / 4) / 256, 256>>>(in_w, wh, wl);
    split_kernel<<<((size_t)E * E / 4) / 256, 256>>>(in_w + 2ULL * E * E, wh + 2ULL * E * E, nullptr);
    split_kernel<<<((size_t)E * E / 4) / 256, 256>>>(out_w, wh + 3ULL * E * E, nullptr);

    // 1) LayerNorms -> split planes
    ln_split<<<Bb * Nn, 256>>>(x, ln_kv_w, ln_kv_b, pos, kvh, kvl, kvph, kvpl);
    ln_split<<<Mm, 256>>>(query, ln_q_w, ln_q_b, pos, nullptr, nullptr, qh, ql);

    // 2) K-proj (y<8) merged with Q-proj (y==8), both 3-pass
    gemm_u<3, true><<<dim3(32, 9, 1), 256, GEMM_SMEM>>>(
        kvph, kvpl, wh + (size_t)E * E, wl + (size_t)E * E, in_b + E, 1.f, nullptr, Kh, Kl,
        0, 0, 0, 0, 0, 0, E, E, E, E / BK,
        qh, ql, wh, wl, in_b, Qh, Ql);

    //    V-proj: 2-pass (drop Wv residual)
    gemm_u<2, false><<<dim3(32, 8, 1), 256, GEMM_SMEM>>>(
        kvh, kvl, wh + 2ULL * E * E, nullptr, in_b + 2 * E, 1.f, nullptr, Vh, Vl,
        0, 0, 0, 0, 0, 0, E, E, E, E / BK,
        nullptr, nullptr, nullptr, nullptr, nullptr, nullptr, nullptr);

    // 3) V transpose -> [bh][d][n]
    vtrans<<<dim3(Dd / 32, Nn / 32, Bb * Hh), 256>>>(Vh, Vl, Vth, Vtl);

    // 4) scores = Q @ K^T / sqrt(D)   (batched over bh), 3-pass
    gemm_u<3, false><<<dim3(2, 1, Bb * Hh), 256, GEMM_SMEM>>>(
        Qh, Ql, Kh, Kl, nullptr, 0.08838834764831845f, attn, nullptr, nullptr,
        (size_t)Dd, 0, (size_t)Dd, (size_t)Nn * E,
        (size_t)Mm * Nn, 32ULL * Mm * Nn, E, E, Nn, Dd / BK,
        nullptr, nullptr, nullptr, nullptr, nullptr, nullptr, nullptr);

    // 5) softmax (+ P planes)
    softmax_kernel<<<Bb * Hh * Mm / 8, 256>>>(attn, Ph, Pl);

    // 6) O = P @ V (batched over bh), 3-pass -> O split planes
    gemm_u<3, false><<<dim3(1, 1, Bb * Hh), 256, GEMM_SMEM>>>(
        Ph, Pl, Vth, Vtl, nullptr, 1.f, nullptr, oh, ol,
        (size_t)Mm * Nn, 32ULL * Mm * Nn, (size_t)Dd * Nn, 32ULL * Dd * Nn,
        (size_t)Dd, (size_t)Mm * E, Nn, Nn, E, Nn / BK,
        nullptr, nullptr, nullptr, nullptr, nullptr, nullptr, nullptr);

    // 7) out projection -> d_out, 2-pass (drop Wo residual)
    gemm_u<2, false><<<dim3(32, 8, 1), 256, GEMM_SMEM>>>(
        oh, ol, wh + 3ULL * E * E, nullptr, out_b, 1.f, out, nullptr, nullptr,
        0, 0, 0, 0, 0, 0, E, E, E, E / BK,
        nullptr, nullptr, nullptr, nullptr, nullptr, nullptr, nullptr);

    // 8) attn.mean(heads)
    attn_mean_kernel<<<Bb * Mm * Nn / 256, 256>>>(attn, out + (size_t)Bb * Mm * E);
}

// round 8
// speedup vs baseline: 4.6414x; 1.1415x over previous
#include <cuda_runtime.h>
#include <cuda_fp16.h>
#include <cstdint>
#include <math.h>

#define E  4096
#define Hh 32
#define Mm 256
#define Bb 8
#define Nn 256
#define Dd 128

// ---------------- scratch (alloc-free: __device__ globals) ----------------
__device__ float g_attn[Bb * Hh * Mm * Nn];

// fp16 hi/lo planes
__device__ __half g_qh[Mm * E],        g_ql[Mm * E];           // LN(query)+pos
__device__ __half g_kvh[Bb * Nn * E],  g_kvl[Bb * Nn * E];     // LN(x)
__device__ __half g_kvph[Bb * Nn * E], g_kvpl[Bb * Nn * E];    // LN(x)+pos
__device__ __half g_Qh[Mm * E],        g_Ql[Mm * E];           // Q proj
__device__ __half g_Kh[Bb * Nn * E],   g_Kl[Bb * Nn * E];      // K proj
__device__ __half g_Vh[Bb * Nn * E],   g_Vl[Bb * Nn * E];      // V proj
__device__ __half g_Vth[Bb * Hh * Dd * Nn], g_Vtl[Bb * Hh * Dd * Nn]; // V^T per (b,h)
__device__ __half g_Ph[Bb * Hh * Mm * Nn],  g_Pl[Bb * Hh * Mm * Nn];  // softmax planes
__device__ __half g_oh[Bb * Mm * E],   g_ol[Bb * Mm * E];      // attn output
__device__ __half g_wh[4ULL * E * E];                          // Wq,Wk,Wv,Wo hi (no lo needed)

// ---------------- helpers ----------------
__device__ __forceinline__ uint32_t smem_u32(const void* p) {
    uint32_t a;
    asm("{ .reg .u64 t; cvta.to.shared.u64 t, %1; cvt.u32.u64 %0, t; }"
        : "=r"(a) : "l"(p));
    return a;
}

__device__ __forceinline__ void cp_async16(uint32_t dst, const void* src) {
    asm volatile("cp.async.cg.shared.global [%0], [%1], 16;"
                 :: "r"(dst), "l"(src) : "memory");
}
#define CP_COMMIT() asm volatile("cp.async.commit_group;" ::: "memory")
#define CP_WAIT1()  asm volatile("cp.async.wait_group 1;" ::: "memory")

__device__ __forceinline__ void mma16816(float* d, const uint32_t* a, const uint32_t* b) {
    asm volatile(
        "mma.sync.aligned.m16n8k16.row.col.f32.f16.f16.f32 "
        "{%0,%1,%2,%3}, {%4,%5,%6,%7}, {%8,%9}, {%0,%1,%2,%3};"
        : "+f"(d[0]), "+f"(d[1]), "+f"(d[2]), "+f"(d[3])
        : "r"(a[0]), "r"(a[1]), "r"(a[2]), "r"(a[3]), "r"(b[0]), "r"(b[1]));
}

__device__ __forceinline__ void split_f4(float4 v, uint2& hi, uint2& lo) {
    __half2 h0 = __floats2half2_rn(v.x, v.y);
    __half2 h1 = __floats2half2_rn(v.z, v.w);
    float2 f0 = __half22float2(h0), f1 = __half22float2(h1);
    __half2 l0 = __floats2half2_rn(v.x - f0.x, v.y - f0.y);
    __half2 l1 = __floats2half2_rn(v.z - f1.x, v.w - f1.y);
    hi.x = *(uint32_t*)&h0; hi.y = *(uint32_t*)&h1;
    lo.x = *(uint32_t*)&l0; lo.y = *(uint32_t*)&l1;
}

__device__ __forceinline__ void split2(float x, float y, uint32_t& h, uint32_t& l) {
    __half2 hh = __floats2half2_rn(x, y);
    float2 f = __half22float2(hh);
    __half2 ll = __floats2half2_rn(x - f.x, y - f.y);
    h = *(uint32_t*)&hh; l = *(uint32_t*)&ll;
}

// ---------------- fp32 -> fp16 hi elementwise (weights; no lo needed) ----------------
__global__ void __launch_bounds__(256) split_hi_kernel(
    const float* __restrict__ src, __half* __restrict__ hi)
{
    size_t i = (size_t)blockIdx.x * 256 + threadIdx.x;
    float4 v = ((const float4*)src)[i];
    __half2 h0 = __floats2half2_rn(v.x, v.y);
    __half2 h1 = __floats2half2_rn(v.z, v.w);
    uint2 h;
    h.x = *(uint32_t*)&h0; h.y = *(uint32_t*)&h1;
    *(uint2*)(hi + i * 4) = h;
}

// ---------------- LayerNorm -> fp16 hi/lo planes (plain and/or +pos) ----------------
__global__ void __launch_bounds__(256) ln_split(
    const float* __restrict__ x, const float* __restrict__ w,
    const float* __restrict__ bias, const float* __restrict__ pos,
    __half* __restrict__ h0, __half* __restrict__ l0,
    __half* __restrict__ hp, __half* __restrict__ lp)
{
    int row = blockIdx.x;
    int tid = threadIdx.x;
    const float4* xr = (const float4*)(x + (size_t)row * E);
    float4 v[4];
    float s = 0.f, sq = 0.f;
#pragma unroll
    for (int i = 0; i < 4; i++) {
        v[i] = xr[tid + 256 * i];
        s  += v[i].x + v[i].y + v[i].z + v[i].w;
        sq += v[i].x * v[i].x + v[i].y * v[i].y + v[i].z * v[i].z + v[i].w * v[i].w;
    }
    __shared__ float s1[256], s2[256];
    s1[tid] = s; s2[tid] = sq;
    __syncthreads();
    for (int st = 128; st > 0; st >>= 1) {
        if (tid < st) { s1[tid] += s1[tid + st]; s2[tid] += s2[tid + st]; }
        __syncthreads();
    }
    float mean = s1[0] * (1.f / E);
    float var  = s2[0] * (1.f / E) - mean * mean;
    float rstd = rsqrtf(var + 1e-5f);

    const float4* wr = (const float4*)w;
    const float4* br = (const float4*)bias;
    const float4* pr = (const float4*)(pos + (size_t)(row & (Nn - 1)) * E);
#pragma unroll
    for (int i = 0; i < 4; i++) {
        int c = tid + 256 * i;
        float4 ww = wr[c], bb = br[c];
        float4 o;
        o.x = (v[i].x - mean) * rstd * ww.x + bb.x;
        o.y = (v[i].y - mean) * rstd * ww.y + bb.y;
        o.z = (v[i].z - mean) * rstd * ww.z + bb.z;
        o.w = (v[i].w - mean) * rstd * ww.w + bb.w;
        size_t off = (size_t)row * E + c * 4;
        uint2 h, l;
        if (h0) {
            split_f4(o, h, l);
            *(uint2*)(h0 + off) = h;
            *(uint2*)(l0 + off) = l;
        }
        if (hp) {
            float4 p = pr[c];
            o.x += p.x; o.y += p.y; o.z += p.z; o.w += p.w;
            split_f4(o, h, l);
            *(uint2*)(hp + off) = h;
            *(uint2*)(lp + off) = l;
        }
    }
}

// ======================= shared pipelined HMMA GEMM body, 256x128 tile =======================
// NPASS=3: C = Ah.Bh + Al.Bh + Ah.Bl ;  NPASS=2: C = Ah.Bh + Al.Bh.
#define BK 64
#define APLANE_B 32768
#define BPLANE_B 16384
#define STAGE_B (2 * APLANE_B + 2 * BPLANE_B)   // 96 KB
#define GEMM_SMEM (2 * STAGE_B)                 // 192 KB

__device__ __forceinline__ uint32_t swo(int row, int col) {
    return (uint32_t)(row * 128 + (((col >> 3) ^ (row & 7)) << 4) + (col & 7) * 2);
}

template <int NPASS>
__device__ __forceinline__ void gemm_body(
    const __half* p0, const __half* p1,   // A hi/lo, already offset to tile row 0
    const __half* p2, const __half* p3,   // B hi/lo, already offset to tile col 0
    const float* bptr, float scale,
    float* ocf, __half* och, __half* ocl, size_t cOff,
    int lda, int ldb, int ldc, int NIT, int m0, int n0, char* sm)
{
    const uint32_t sbase = smem_u32(sm);
    const int tid  = threadIdx.x;
    const int wid  = tid >> 5;
    const int lane = tid & 31;
    const int g    = lane >> 2;
    const int tq   = lane & 3;
    const int wm   = (wid >> 1) * 64;
    const int wn   = (wid & 1) * 64;

    float acc[4][8][4];
#pragma unroll
    for (int i = 0; i < 4; i++)
#pragma unroll
        for (int j = 0; j < 8; j++)
#pragma unroll
            for (int k = 0; k < 4; k++) acc[i][j][k] = 0.f;

    auto issue = [&](int slot, int kt) {
        uint32_t sb = sbase + slot * STAGE_B;
#pragma unroll
        for (int j = 0; j < 8; j++) {
            int idx = tid + 256 * j;
            int row = idx >> 3;
            int c   = idx & 7;
            uint32_t so = row * 128 + ((c ^ (row & 7)) << 4);
            cp_async16(sb + so, p0 + (size_t)row * lda + kt + c * 8);
            cp_async16(sb + APLANE_B + so, p1 + (size_t)row * lda + kt + c * 8);
        }
#pragma unroll
        for (int j = 0; j < 4; j++) {
            int idx = tid + 256 * j;
            int row = idx >> 3;
            int c   = idx & 7;
            uint32_t so = row * 128 + ((c ^ (row & 7)) << 4);
            cp_async16(sb + 2 * APLANE_B + so, p2 + (size_t)row * ldb + kt + c * 8);
            if (NPASS == 3)
                cp_async16(sb + 2 * APLANE_B + BPLANE_B + so, p3 + (size_t)row * ldb + kt + c * 8);
        }
    };

    issue(0, 0);  CP_COMMIT();
    if (NIT > 1) issue(1, BK);
    CP_COMMIT();

    for (int it = 0; it < NIT; it++) {
        CP_WAIT1();
        __syncthreads();

        const char* base = sm + (it & 1) * STAGE_B;
        const char* Ahs = base;
        const char* Als = base + APLANE_B;
        const char* Bhs = base + 2 * APLANE_B;
        const char* Bls = base + 2 * APLANE_B + BPLANE_B;
#pragma unroll
        for (int ks = 0; ks < BK; ks += 16) {
            uint32_t ah[4][4], al[4][4], bf[8][2];
#pragma unroll
            for (int mt = 0; mt < 4; mt++)
#pragma unroll
                for (int r = 0; r < 4; r++) {
                    int row = wm + mt * 16 + g + (r & 1) * 8;
                    int col = ks + tq * 2 + (r >> 1) * 8;
                    ah[mt][r] = *(const uint32_t*)(Ahs + swo(row, col));
                    al[mt][r] = *(const uint32_t*)(Als + swo(row, col));
                }
#pragma unroll
            for (int nt = 0; nt < 8; nt++) {
                int row = wn + nt * 8 + g;
                bf[nt][0] = *(const uint32_t*)(Bhs + swo(row, ks + tq * 2));
                bf[nt][1] = *(const uint32_t*)(Bhs + swo(row, ks + tq * 2 + 8));
            }
#pragma unroll
            for (int mt = 0; mt < 4; mt++)
#pragma unroll
                for (int nt = 0; nt < 8; nt++) mma16816(acc[mt][nt], ah[mt], bf[nt]);
#pragma unroll
            for (int mt = 0; mt < 4; mt++)
#pragma unroll
                for (int nt = 0; nt < 8; nt++) mma16816(acc[mt][nt], al[mt], bf[nt]);
            if (NPASS == 3) {
#pragma unroll
                for (int nt = 0; nt < 8; nt++) {
                    int row = wn + nt * 8 + g;
                    bf[nt][0] = *(const uint32_t*)(Bls + swo(row, ks + tq * 2));
                    bf[nt][1] = *(const uint32_t*)(Bls + swo(row, ks + tq * 2 + 8));
                }
#pragma unroll
                for (int mt = 0; mt < 4; mt++)
#pragma unroll
                    for (int nt = 0; nt < 8; nt++) mma16816(acc[mt][nt], ah[mt], bf[nt]);
            }
        }
        __syncthreads();
        if (it + 2 < NIT) issue((it + 2) & 1, (it + 2) * BK);
        CP_COMMIT();
    }

    // epilogue
    float bn[8][2];
#pragma unroll
    for (int nt = 0; nt < 8; nt++) {
        if (bptr) {
            int n = n0 + wn + nt * 8 + tq * 2;
            bn[nt][0] = bptr[n];
            bn[nt][1] = bptr[n + 1];
        } else {
            bn[nt][0] = 0.f; bn[nt][1] = 0.f;
        }
    }
#pragma unroll
    for (int mt = 0; mt < 4; mt++)
#pragma unroll
        for (int half = 0; half < 2; half++) {
            int m = m0 + wm + mt * 16 + g + half * 8;
#pragma unroll
            for (int nt = 0; nt < 8; nt++) {
                float vx = acc[mt][nt][half * 2 + 0] * scale + bn[nt][0];
                float vy = acc[mt][nt][half * 2 + 1] * scale + bn[nt][1];
                size_t off = cOff + (size_t)m * ldc + n0 + wn + nt * 8 + tq * 2;
                if (ocf) *(float2*)(ocf + off) = make_float2(vx, vy);
                if (och) {
                    uint32_t h, l;
                    split2(vx, vy, h, l);
                    *(uint32_t*)(och + off) = h;
                    *(uint32_t*)(ocl + off) = l;
                }
            }
        }
}

// ---------------- merged K/Q/V projection launch (all 2-pass) ----------------
// grid = (32, 17): y in [0,8) K-proj, y == 8 Q-proj, y in [9,17) V-proj.
__global__ void __launch_bounds__(256, 1) proj_kernel(
    const __half* __restrict__ kvph, const __half* __restrict__ kvpl,
    const __half* __restrict__ qh,   const __half* __restrict__ ql,
    const __half* __restrict__ kvh,  const __half* __restrict__ kvl,
    const __half* __restrict__ wh,   const float* __restrict__ in_b,
    __half* __restrict__ Kh, __half* __restrict__ Kl,
    __half* __restrict__ Qh, __half* __restrict__ Ql,
    __half* __restrict__ Vh, __half* __restrict__ Vl)
{
    extern __shared__ char sm[];
    const int y = blockIdx.y;
    const int n0 = blockIdx.x * 128;
    const __half *a0, *a1, *b0;
    const float* bp;
    __half *ch, *cl;
    int m0;
    if (y < 8) {              // K projection
        m0 = y * 256;
        a0 = kvph + (size_t)m0 * E; a1 = kvpl + (size_t)m0 * E;
        b0 = wh + (size_t)E * E + (size_t)n0 * E;
        bp = in_b + E; ch = Kh; cl = Kl;
    } else if (y == 8) {      // Q projection (M=256 total)
        m0 = 0;
        a0 = qh; a1 = ql;
        b0 = wh + (size_t)n0 * E;
        bp = in_b; ch = Qh; cl = Ql;
    } else {                  // V projection
        m0 = (y - 9) * 256;
        a0 = kvh + (size_t)m0 * E; a1 = kvl + (size_t)m0 * E;
        b0 = wh + 2ULL * E * E + (size_t)n0 * E;
        bp = in_b + 2 * E; ch = Vh; cl = Vl;
    }
    gemm_body<2>(a0, a1, b0, nullptr, bp, 1.f, nullptr, ch, cl, 0,
                 E, E, E, E / BK, m0, n0, sm);
}

// ---------------- generic batched GEMM (scores / PV / out-proj) ----------------
template <int NPASS>
__global__ void __launch_bounds__(256, 1) gemm_b(
    const __half* __restrict__ Ahp, const __half* __restrict__ Alp,
    const __half* __restrict__ Bhp, const __half* __restrict__ Blp,
    const float* __restrict__ bias, float scale,
    float* __restrict__ Cf, __half* __restrict__ Ch, __half* __restrict__ Cl,
    size_t aSH, size_t aSB, size_t bSH, size_t bSB, size_t cSH, size_t cSB,
    int lda, int ldb, int ldc, int NIT)
{
    extern __shared__ char sm[];
    const int m0 = blockIdx.y * 256;
    const int n0 = blockIdx.x * 128;
    const int z  = blockIdx.z;
    const int hz = z & 31, bz = z >> 5;
    const size_t aOff = (size_t)hz * aSH + (size_t)bz * aSB;
    const size_t bOff = (size_t)hz * bSH + (size_t)bz * bSB;
    const size_t cOff = (size_t)hz * cSH + (size_t)bz * cSB;
    gemm_body<NPASS>(
        Ahp + aOff + (size_t)m0 * lda, Alp + aOff + (size_t)m0 * lda,
        Bhp + bOff + (size_t)n0 * ldb,
        (NPASS == 3) ? Blp + bOff + (size_t)n0 * ldb : nullptr,
        bias, scale, Cf, Ch, Cl, cOff, lda, ldb, ldc, NIT, m0, n0, sm);
}

// ---------------- V planes -> V^T planes per (b,h): [n][d] -> [d][n] ----------------
__global__ void __launch_bounds__(256) vtrans(
    const __half* __restrict__ Vh, const __half* __restrict__ Vl,
    __half* __restrict__ Vth, __half* __restrict__ Vtl)
{
    __shared__ __half t0[32][33], t1[32][33];
    int z = blockIdx.z;
    int hz = z & 31, bz = z >> 5;
    int d0 = blockIdx.x * 32;
    int n0 = blockIdx.y * 32;
    int tx = threadIdx.x & 31, ty = threadIdx.x >> 5;
#pragma unroll
    for (int i = 0; i < 4; i++) {
        int n = n0 + ty + i * 8;
        size_t src = ((size_t)bz * Nn + n) * E + hz * Dd + d0 + tx;
        t0[ty + i * 8][tx] = Vh[src];
        t1[ty + i * 8][tx] = Vl[src];
    }
    __syncthreads();
#pragma unroll
    for (int i = 0; i < 4; i++) {
        int d = d0 + ty + i * 8;
        size_t dst = ((size_t)z * Dd + d) * Nn + n0 + tx;
        Vth[dst] = t0[tx][ty + i * 8];
        Vtl[dst] = t1[tx][ty + i * 8];
    }
}

// ---------------- softmax over n; writes fp32 in-place + fp16 hi/lo planes ----------------
__global__ void __launch_bounds__(256) softmax_kernel(
    float* __restrict__ attn,
    __half* __restrict__ Ph, __half* __restrict__ Pl)
{
    int warp = threadIdx.x >> 5, lane = threadIdx.x & 31;
    size_t row = (size_t)blockIdx.x * 8 + warp;
    float4* p = (float4*)(attn + row * Nn);
    float4 v0 = p[lane];
    float4 v1 = p[lane + 32];
    float mx = fmaxf(fmaxf(fmaxf(v0.x, v0.y), fmaxf(v0.z, v0.w)),
                     fmaxf(fmaxf(v1.x, v1.y), fmaxf(v1.z, v1.w)));
#pragma unroll
    for (int o = 16; o; o >>= 1) mx = fmaxf(mx, __shfl_xor_sync(0xffffffffu, mx, o));
    v0.x = expf(v0.x - mx); v0.y = expf(v0.y - mx);
    v0.z = expf(v0.z - mx); v0.w = expf(v0.w - mx);
    v1.x = expf(v1.x - mx); v1.y = expf(v1.y - mx);
    v1.z = expf(v1.z - mx); v1.w = expf(v1.w - mx);
    float s = v0.x + v0.y + v0.z + v0.w + v1.x + v1.y + v1.z + v1.w;
#pragma unroll
    for (int o = 16; o; o >>= 1) s += __shfl_xor_sync(0xffffffffu, s, o);
    float inv = 1.f / s;
    v0.x *= inv; v0.y *= inv; v0.z *= inv; v0.w *= inv;
    v1.x *= inv; v1.y *= inv; v1.z *= inv; v1.w *= inv;
    p[lane] = v0;
    p[lane + 32] = v1;
    uint2 h, l;
    split_f4(v0, h, l);
    *(uint2*)(Ph + row * Nn + lane * 4) = h;
    *(uint2*)(Pl + row * Nn + lane * 4) = l;
    split_f4(v1, h, l);
    *(uint2*)(Ph + row * Nn + 128 + lane * 4) = h;
    *(uint2*)(Pl + row * Nn + 128 + lane * 4) = l;
}

// ---------------- attn mean over heads ----------------
__global__ void __launch_bounds__(256) attn_mean_kernel(
    const float* __restrict__ attn, float* __restrict__ out)
{
    int idx = blockIdx.x * 256 + threadIdx.x;
    int b = idx / (Mm * Nn);
    int rem = idx - b * (Mm * Nn);
    const float* p = attn + (size_t)b * Hh * Mm * Nn + rem;
    float s = 0.f;
#pragma unroll
    for (int h = 0; h < Hh; h++) s += p[(size_t)h * Mm * Nn];
    out[idx] = s * (1.f / Hh);
}

// ---------------- launcher ----------------
extern "C" void kernel_launch(void* const* d_in, const int* in_sizes, int n_in,
                              void* d_out, int out_size)
{
    const float* x       = (const float*)d_in[0];
    const float* query   = (const float*)d_in[1];
    const float* pos     = (const float*)d_in[2];
    const float* ln_q_w  = (const float*)d_in[3];
    const float* ln_q_b  = (const float*)d_in[4];
    const float* ln_kv_w = (const float*)d_in[5];
    const float* ln_kv_b = (const float*)d_in[6];
    const float* in_w    = (const float*)d_in[7];
    const float* in_b    = (const float*)d_in[8];
    const float* out_w   = (const float*)d_in[9];
    const float* out_b   = (const float*)d_in[10];
    float* out = (float*)d_out;

    float *attn;
    cudaGetSymbolAddress((void**)&attn, g_attn);
    __half *qh, *ql, *kvh, *kvl, *kvph, *kvpl;
    __half *Qh, *Ql, *Kh, *Kl, *Vh, *Vl, *Vth, *Vtl, *Ph, *Pl, *oh, *ol, *wh;
    cudaGetSymbolAddress((void**)&qh,   g_qh);
    cudaGetSymbolAddress((void**)&ql,   g_ql);
    cudaGetSymbolAddress((void**)&kvh,  g_kvh);
    cudaGetSymbolAddress((void**)&kvl,  g_kvl);
    cudaGetSymbolAddress((void**)&kvph, g_kvph);
    cudaGetSymbolAddress((void**)&kvpl, g_kvpl);
    cudaGetSymbolAddress((void**)&Qh,   g_Qh);
    cudaGetSymbolAddress((void**)&Ql,   g_Ql);
    cudaGetSymbolAddress((void**)&Kh,   g_Kh);
    cudaGetSymbolAddress((void**)&Kl,   g_Kl);
    cudaGetSymbolAddress((void**)&Vh,   g_Vh);
    cudaGetSymbolAddress((void**)&Vl,   g_Vl);
    cudaGetSymbolAddress((void**)&Vth,  g_Vth);
    cudaGetSymbolAddress((void**)&Vtl,  g_Vtl);
    cudaGetSymbolAddress((void**)&Ph,   g_Ph);
    cudaGetSymbolAddress((void**)&Pl,   g_Pl);
    cudaGetSymbolAddress((void**)&oh,   g_oh);
    cudaGetSymbolAddress((void**)&ol,   g_ol);
    cudaGetSymbolAddress((void**)&wh,   g_wh);

    cudaFuncSetAttribute(proj_kernel, cudaFuncAttributeMaxDynamicSharedMemorySize, GEMM_SMEM);
    cudaFuncSetAttribute(gemm_b<3>,   cudaFuncAttributeMaxDynamicSharedMemorySize, GEMM_SMEM);
    cudaFuncSetAttribute(gemm_b<2>,   cudaFuncAttributeMaxDynamicSharedMemorySize, GEMM_SMEM);

    // 0) split weights (hi only — all projection GEMMs are 2-pass on weights)
    split_hi_kernel<<<(3ULL * E * E / 4) / 256, 256>>>(in_w, wh);
    split_hi_kernel<<<((size_t)E * E / 4) / 256, 256>>>(out_w, wh + 3ULL * E * E);

    // 1) LayerNorms -> split planes
    ln_split<<<Bb * Nn, 256>>>(x, ln_kv_w, ln_kv_b, pos, kvh, kvl, kvph, kvpl);
    ln_split<<<Mm, 256>>>(query, ln_q_w, ln_q_b, pos, nullptr, nullptr, qh, ql);

    // 2) Merged K/Q/V projections (one launch, 544 CTAs, 2-pass each)
    proj_kernel<<<dim3(32, 17, 1), 256, GEMM_SMEM>>>(
        kvph, kvpl, qh, ql, kvh, kvl, wh, in_b, Kh, Kl, Qh, Ql, Vh, Vl);

    // 3) V transpose -> [bh][d][n]
    vtrans<<<dim3(Dd / 32, Nn / 32, Bb * Hh), 256>>>(Vh, Vl, Vth, Vtl);

    // 4) scores = Q @ K^T / sqrt(D)   (batched over bh), 3-pass
    gemm_b<3><<<dim3(2, 1, Bb * Hh), 256, GEMM_SMEM>>>(
        Qh, Ql, Kh, Kl, nullptr, 0.08838834764831845f, attn, nullptr, nullptr,
        (size_t)Dd, 0, (size_t)Dd, (size_t)Nn * E,
        (size_t)Mm * Nn, 32ULL * Mm * Nn, E, E, Nn, Dd / BK);

    // 5) softmax (+ P planes)
    softmax_kernel<<<Bb * Hh * Mm / 8, 256>>>(attn, Ph, Pl);

    // 6) O = P @ V (batched over bh), 3-pass -> O split planes
    gemm_b<3><<<dim3(1, 1, Bb * Hh), 256, GEMM_SMEM>>>(
        Ph, Pl, Vth, Vtl, nullptr, 1.f, nullptr, oh, ol,
        (size_t)Mm * Nn, 32ULL * Mm * Nn, (size_t)Dd * Nn, 32ULL * Dd * Nn,
        (size_t)Dd, (size_t)Mm * E, Nn, Nn, E, Nn / BK);

    // 7) out projection -> d_out, 2-pass
    gemm_b<2><<<dim3(32, 8, 1), 256, GEMM_SMEM>>>(
        oh, ol, wh + 3ULL * E * E, nullptr, out_b, 1.f, out, nullptr, nullptr,
        0, 0, 0, 0, 0, 0, E, E, E, E / BK);

    // 8) attn.mean(heads)
    attn_mean_kernel<<<Bb * Mm * Nn / 256, 256>>>(attn, out + (size_t)Bb * Mm * E);
}